// round 6
// baseline (speedup 1.0000x reference)
#include <cuda_runtime.h>
#include <math.h>
#include <stdint.h>

#define TT 384
#define CC 512
#define HH 8
#define DD 64
#define EE 16

// ---------------- scratch (device globals; no allocs allowed) ----------------
__device__ float g_h  [TT*CC];        // LN1 output
__device__ float g_qkv[TT*3*CC];      // QKV
__device__ float g_EV [EE*CC];        // edge-v table
__device__ float g_EKt[CC*EE];        // edge-k table transposed: [c][e]
__device__ float g_Kt [CC*TT];        // K transposed: [c][j]
__device__ float g_y  [TT*CC];        // attention output (pre-proj)
__device__ float g_x1 [TT*CC];        // x + attn
__device__ float g_h2 [TT*CC];        // LN2 output
__device__ float g_fc [TT*4*CC];      // GELU(fc)

// ---------------- cp.async helpers ------------------------------------------
__device__ __forceinline__ void cp16(void* smem, const void* gmem) {
    uint32_t s = (uint32_t)__cvta_generic_to_shared(smem);
    asm volatile("cp.async.cg.shared.global [%0], [%1], 16;\n" :: "r"(s), "l"(gmem));
}
__device__ __forceinline__ void cp_commit() {
    asm volatile("cp.async.commit_group;\n");
}
template<int N>
__device__ __forceinline__ void cp_wait() {
    asm volatile("cp.async.wait_group %0;\n" :: "n"(N));
}

// ---------------- edge table precompute: EK/EV = edge_emb @ W^T + b ----------
__global__ void edge_pre(const float* __restrict__ emb,
                         const float* __restrict__ Wk, const float* __restrict__ bk,
                         const float* __restrict__ Wv, const float* __restrict__ bv,
                         float* __restrict__ EKt, float* __restrict__ EV) {
    int e = blockIdx.x;           // 16 blocks
    int n = threadIdx.x;          // 512 threads
    __shared__ float er[CC];
    er[n] = emb[e*CC + n];
    __syncthreads();
    const float4* wk = (const float4*)(Wk + n*CC);
    const float4* wv = (const float4*)(Wv + n*CC);
    float sk = 0.f, sv = 0.f;
    #pragma unroll 4
    for (int k = 0; k < CC/4; k++) {
        float4 a = wk[k], b = wv[k];
        float e0 = er[4*k+0], e1 = er[4*k+1], e2 = er[4*k+2], e3 = er[4*k+3];
        sk = fmaf(e0,a.x, fmaf(e1,a.y, fmaf(e2,a.z, fmaf(e3,a.w, sk))));
        sv = fmaf(e0,b.x, fmaf(e1,b.y, fmaf(e2,b.z, fmaf(e3,b.w, sv))));
    }
    EKt[n*EE + e] = sk + bk[n];
    EV [e*CC + n] = sv + bv[n];
}

// ---------------- layernorm (row of 512, 256 threads/row) -------------------
__global__ void ln_kernel(const float* __restrict__ x, const float* __restrict__ w,
                          const float* __restrict__ b, float* __restrict__ out) {
    int row = blockIdx.x;
    int tid = threadIdx.x;                 // 256
    int lane = tid & 31, wid = tid >> 5;
    const float* xr = x + row*CC;
    float v0 = xr[tid], v1 = xr[tid + 256];

    __shared__ float rbuf[8];
    __shared__ float stats[2];

    float s = v0 + v1;
    #pragma unroll
    for (int o = 16; o > 0; o >>= 1) s += __shfl_xor_sync(0xffffffffu, s, o);
    if (lane == 0) rbuf[wid] = s;
    __syncthreads();
    if (tid == 0) {
        float t = 0.f;
        #pragma unroll
        for (int i = 0; i < 8; i++) t += rbuf[i];
        stats[0] = t * (1.0f/CC);
    }
    __syncthreads();
    float mu = stats[0];
    float d0 = v0 - mu, d1 = v1 - mu;
    float q = d0*d0 + d1*d1;
    #pragma unroll
    for (int o = 16; o > 0; o >>= 1) q += __shfl_xor_sync(0xffffffffu, q, o);
    if (lane == 0) rbuf[wid] = q;
    __syncthreads();
    if (tid == 0) {
        float t = 0.f;
        #pragma unroll
        for (int i = 0; i < 8; i++) t += rbuf[i];
        stats[1] = rsqrtf(t * (1.0f/CC) + 1e-5f);
    }
    __syncthreads();
    float rstd = stats[1];
    out[row*CC + tid]       = d0 * rstd * w[tid]       + b[tid];
    out[row*CC + tid + 256] = d1 * rstd * w[tid + 256] + b[tid + 256];
}

// ---------------- tf32 tensor-core NT GEMM, cp.async 4-stage pipeline --------
// C[m,n] = sum_k A[m,k]*B[n,k] + bias[n] ; EPI: 0=bias, 1=bias+res, 2=bias+GELU
// BN=64, BK=16. BM=64/NTHR=256 (8 warps 2x4) or BM=32/NTHR=128 (4 warps 2x2).
__device__ __forceinline__ void mma_tf32(float c[4], const uint32_t a[4], const uint32_t b[2]) {
    asm volatile(
        "mma.sync.aligned.m16n8k8.row.col.f32.tf32.tf32.f32 "
        "{%0,%1,%2,%3}, {%4,%5,%6,%7}, {%8,%9}, {%0,%1,%2,%3};\n"
        : "+f"(c[0]), "+f"(c[1]), "+f"(c[2]), "+f"(c[3])
        : "r"(a[0]), "r"(a[1]), "r"(a[2]), "r"(a[3]), "r"(b[0]), "r"(b[1]));
}
__device__ __forceinline__ uint32_t f2tf32(float x) {
    uint32_t r;
    asm("cvt.rna.tf32.f32 %0, %1;\n" : "=r"(r) : "f"(x));
    return r;
}
__device__ __forceinline__ float epi_apply(float v, float r, int EPI) {
    if (EPI == 1) v += r;
    if (EPI == 2) v = 0.5f * v * (1.0f + erff(v * 0.70710678118654752f));
    return v;
}

template<int BM, int NTHR, int EPI, bool WKT>
__global__ void __launch_bounds__(NTHR)
gemm_tc(const float* __restrict__ A, const float* __restrict__ B,
        const float* __restrict__ bias, const float* __restrict__ res,
        float* __restrict__ Cout, float* __restrict__ Kt,
        int M, int N, int K) {
    constexpr int BN = 64, BK = 16, PAD = 20;   // 20 words: 16B-aligned rows, conflict-free
    constexpr int MI  = BM / 32;                // m16 frags per warp
    constexpr int NWN = NTHR / 64;              // warps along n
    constexpr int NI  = BN / (8 * NWN);         // n8 frags per warp
    constexpr int CA  = (BM * 4) / NTHR;        // float4 chunks per thread (A)
    constexpr int CB  = (BN * 4) / NTHR;        // (B)

    __shared__ float As[4][BM][PAD];
    __shared__ float Bs[4][BN][PAD];

    int tid = threadIdx.x;
    int warp = tid >> 5, lane = tid & 31;
    int wm = warp & 1, wn = warp >> 1;
    int qr = lane >> 2, qc = lane & 3;
    int bm = blockIdx.y * BM, bn = blockIdx.x * BN;

    const int KT = K >> 4;

    float acc[MI][NI][4] = {};

    auto loadtile = [&](int st, int k0) {
        #pragma unroll
        for (int c = 0; c < CA; c++) {
            int ch = tid + c*NTHR;
            int r = ch >> 2, c4 = (ch & 3) << 2;
            cp16(&As[st][r][c4], A + (size_t)(bm + r)*K + k0 + c4);
        }
        #pragma unroll
        for (int c = 0; c < CB; c++) {
            int ch = tid + c*NTHR;
            int r = ch >> 2, c4 = (ch & 3) << 2;
            cp16(&Bs[st][r][c4], B + (size_t)(bn + r)*K + k0 + c4);
        }
    };

    loadtile(0, 0);  cp_commit();
    loadtile(1, 16); cp_commit();
    loadtile(2, 32); cp_commit();

    for (int kt = 0; kt < KT; kt++) {
        cp_wait<2>();
        __syncthreads();
        if (kt + 3 < KT) { loadtile((kt + 3) & 3, (kt + 3) << 4); }
        cp_commit();
        int st = kt & 3;
        #pragma unroll
        for (int ko = 0; ko < 16; ko += 8) {
            uint32_t af[MI][4];
            #pragma unroll
            for (int mi = 0; mi < MI; mi++) {
                int row = wm*(MI*16) + mi*16 + qr;
                af[mi][0] = f2tf32(As[st][row    ][ko + qc]);
                af[mi][1] = f2tf32(As[st][row + 8][ko + qc]);
                af[mi][2] = f2tf32(As[st][row    ][ko + 4 + qc]);
                af[mi][3] = f2tf32(As[st][row + 8][ko + 4 + qc]);
            }
            uint32_t bf[NI][2];
            #pragma unroll
            for (int ni = 0; ni < NI; ni++) {
                int col = wn*(NI*8) + ni*8 + qr;
                bf[ni][0] = f2tf32(Bs[st][col][ko + qc]);
                bf[ni][1] = f2tf32(Bs[st][col][ko + 4 + qc]);
            }
            #pragma unroll
            for (int mi = 0; mi < MI; mi++)
                #pragma unroll
                for (int ni = 0; ni < NI; ni++)
                    mma_tf32(acc[mi][ni], af[mi], bf[ni]);
        }
        __syncthreads();
    }

    // epilogue
    #pragma unroll
    for (int mi = 0; mi < MI; mi++) {
        int row0 = bm + wm*(MI*16) + mi*16 + qr;
        #pragma unroll
        for (int ni = 0; ni < NI; ni++) {
            int col = bn + wn*(NI*8) + ni*8 + qc*2;
            float b0 = bias[col], b1 = bias[col + 1];
            float* cp0 = Cout + (size_t)row0*N + col;
            float* cp1 = Cout + (size_t)(row0 + 8)*N + col;
            float r00 = 0.f, r01 = 0.f, r10 = 0.f, r11 = 0.f;
            if (EPI == 1) {
                const float* rp0 = res + (size_t)row0*N + col;
                const float* rp1 = res + (size_t)(row0 + 8)*N + col;
                r00 = rp0[0]; r01 = rp0[1]; r10 = rp1[0]; r11 = rp1[1];
            }
            float2 o0, o1;
            o0.x = epi_apply(acc[mi][ni][0] + b0, r00, EPI);
            o0.y = epi_apply(acc[mi][ni][1] + b1, r01, EPI);
            o1.x = epi_apply(acc[mi][ni][2] + b0, r10, EPI);
            o1.y = epi_apply(acc[mi][ni][3] + b1, r11, EPI);
            *(float2*)cp0 = o0;
            *(float2*)cp1 = o1;
            if (WKT && col >= CC && col < 2*CC) {   // fused K transpose
                int kc = col - CC;
                Kt[(size_t)kc*TT + row0]           = o0.x;
                Kt[(size_t)(kc + 1)*TT + row0]     = o0.y;
                Kt[(size_t)kc*TT + row0 + 8]       = o1.x;
                Kt[(size_t)(kc + 1)*TT + row0 + 8] = o1.y;
            }
        }
    }
}

// ---------------- gather attention: block per (i, h), 128 threads ------------
__global__ void attn2(const float* __restrict__ qkv, const float* __restrict__ Kt,
                      const int* __restrict__ bm,
                      const float* __restrict__ EKt, const float* __restrict__ EV,
                      const float* __restrict__ abe, float* __restrict__ y) {
    int i = TT - 1 - blockIdx.x;          // heavy blocks first
    int h = blockIdx.y;
    int tid = threadIdx.x;                // 128
    int lane = tid & 31, wid = tid >> 5;

    __shared__ float qe_s[DD*EE];         // [d][e] = q[d]*EK[e][d]
    __shared__ float EV_s[EE*DD];         // [e][d]
    __shared__ float ab_s[EE];
    __shared__ float s_s[TT];
    __shared__ int   e_s[TT];
    __shared__ float psum[2][DD];
    __shared__ float rbuf[4];
    __shared__ float resv[2];

    const float* EKh = EKt + h*DD*EE;
    #pragma unroll
    for (int k = 0; k < 8; k++) {         // 1024 / 128
        int idx = tid + k*128;
        int d = idx >> 4;
        qe_s[idx] = qkv[(size_t)i*3*CC + h*DD + d] * EKh[idx];
        EV_s[idx] = EV[(size_t)(idx >> 6)*CC + h*DD + (idx & 63)];
    }
    if (tid < EE) ab_s[tid] = abe[tid*HH + h];
    __syncthreads();

    // pass 1: thread-per-j dot products against transposed K
    const float* KtH = Kt + (size_t)h*DD*TT;
    for (int j = tid; j <= i; j += 128) {
        int e = bm[i*TT + j];
        const float* kp = KtH + j;
        float s = 0.f;
        #pragma unroll 16
        for (int d = 0; d < DD; d++)
            s = fmaf(qe_s[d*EE + e], kp[(size_t)d*TT], s);
        s_s[j] = s * 0.125f + ab_s[e];
        e_s[j] = e;
    }
    __syncthreads();

    // block max
    float lm = -1e30f;
    for (int j = tid; j <= i; j += 128) lm = fmaxf(lm, s_s[j]);
    #pragma unroll
    for (int o = 16; o > 0; o >>= 1) lm = fmaxf(lm, __shfl_xor_sync(0xffffffffu, lm, o));
    if (lane == 0) rbuf[wid] = lm;
    __syncthreads();
    if (tid == 0) resv[0] = fmaxf(fmaxf(rbuf[0], rbuf[1]), fmaxf(rbuf[2], rbuf[3]));
    __syncthreads();
    float m = resv[0];

    // exp + sum
    float ls = 0.f;
    for (int j = tid; j <= i; j += 128) {
        float p = __expf(s_s[j] - m);
        s_s[j] = p;
        ls += p;
    }
    #pragma unroll
    for (int o = 16; o > 0; o >>= 1) ls += __shfl_xor_sync(0xffffffffu, ls, o);
    if (lane == 0) rbuf[wid] = ls;
    __syncthreads();
    if (tid == 0) resv[1] = 1.0f / (rbuf[0] + rbuf[1] + rbuf[2] + rbuf[3]);
    __syncthreads();
    float inv = resv[1];

    // pass 2: weighted V accumulate
    int d = tid & 63, half = tid >> 6;
    float acc = 0.f;
    for (int j = half; j <= i; j += 2) {
        int e = e_s[j];
        acc = fmaf(s_s[j], qkv[(size_t)j*3*CC + 2*CC + h*DD + d] * EV_s[e*DD + d], acc);
    }
    psum[half][d] = acc;
    __syncthreads();
    if (tid < DD) y[(size_t)i*CC + h*DD + tid] = (psum[0][tid] + psum[1][tid]) * inv;
}

// ---------------- host launch ------------------------------------------------
extern "C" void kernel_launch(void* const* d_in, const int* in_sizes, int n_in,
                              void* d_out, int out_size) {
    const float* x        = (const float*)d_in[0];
    const int*   bmx      = (const int*)  d_in[1];
    const float* ln1_w    = (const float*)d_in[2];
    const float* ln1_b    = (const float*)d_in[3];
    const float* w_attn_w = (const float*)d_in[4];
    const float* w_attn_b = (const float*)d_in[5];
    const float* w_proj_w = (const float*)d_in[6];
    const float* w_proj_b = (const float*)d_in[7];
    const float* abe      = (const float*)d_in[8];
    const float* edge_emb = (const float*)d_in[9];
    const float* wek      = (const float*)d_in[10];
    const float* bek      = (const float*)d_in[11];
    const float* wev      = (const float*)d_in[12];
    const float* bev      = (const float*)d_in[13];
    const float* ln2_w    = (const float*)d_in[14];
    const float* ln2_b    = (const float*)d_in[15];
    const float* c_fc_w   = (const float*)d_in[16];
    const float* c_fc_b   = (const float*)d_in[17];
    const float* c_proj_w = (const float*)d_in[18];
    const float* c_proj_b = (const float*)d_in[19];
    float* out = (float*)d_out;

    float *pH, *pQKV, *pEKt, *pEV, *pKt, *pY, *pX1, *pH2, *pFC;
    cudaGetSymbolAddress((void**)&pH,   g_h);
    cudaGetSymbolAddress((void**)&pQKV, g_qkv);
    cudaGetSymbolAddress((void**)&pEKt, g_EKt);
    cudaGetSymbolAddress((void**)&pEV,  g_EV);
    cudaGetSymbolAddress((void**)&pKt,  g_Kt);
    cudaGetSymbolAddress((void**)&pY,   g_y);
    cudaGetSymbolAddress((void**)&pX1,  g_x1);
    cudaGetSymbolAddress((void**)&pH2,  g_h2);
    cudaGetSymbolAddress((void**)&pFC,  g_fc);

    // 1. edge tables
    edge_pre<<<EE, CC>>>(edge_emb, wek, bek, wev, bev, pEKt, pEV);
    // 2. LN1
    ln_kernel<<<TT, 256>>>(x, ln1_w, ln1_b, pH);
    // 3. QKV = LN1 @ w_attn^T + b (384 x 1536 x 512), fused K-transpose
    gemm_tc<64,256,0,true><<<dim3(3*CC/64, TT/64), 256>>>(pH, w_attn_w, w_attn_b, nullptr, pQKV, pKt, TT, 3*CC, CC);
    // 4. gather attention
    attn2<<<dim3(TT, HH), 128>>>(pQKV, pKt, bmx, pEKt, pEV, abe, pY);
    // 5. x1 = x + y @ w_proj^T + b (384 x 512 x 512)
    gemm_tc<32,128,1,false><<<dim3(CC/64, TT/32), 128>>>(pY, w_proj_w, w_proj_b, x, pX1, nullptr, TT, CC, CC);
    // 6. LN2
    ln_kernel<<<TT, 256>>>(pX1, ln2_w, ln2_b, pH2);
    // 7. fc = gelu(h2 @ c_fc^T + b) (384 x 2048 x 512)
    gemm_tc<64,256,2,false><<<dim3(4*CC/64, TT/64), 256>>>(pH2, c_fc_w, c_fc_b, nullptr, pFC, nullptr, TT, 4*CC, CC);
    // 8. out = x1 + fc @ c_proj^T + b (384 x 512 x 2048)
    gemm_tc<32,128,1,false><<<dim3(CC/64, TT/32), 128>>>(pFC, c_proj_w, c_proj_b, pX1, out, nullptr, TT, CC, 4*CC);
}

// round 8
// speedup vs baseline: 1.0287x; 1.0287x over previous
#include <cuda_runtime.h>
#include <math.h>
#include <stdint.h>

#define TT 384
#define CC 512
#define HH 8
#define DD 64
#define EE 16

// ---------------- scratch (device globals; no allocs allowed) ----------------
__device__ float g_h  [TT*CC];        // LN1 output
__device__ float g_qkv[TT*3*CC];      // QKV
__device__ float g_EK [EE*CC];        // edge-k table [e][c]
__device__ float g_EV [EE*CC];        // edge-v table [e][c]
__device__ float g_y  [TT*CC];        // attention output (pre-proj)
__device__ float g_x1 [TT*CC];        // x + attn
__device__ float g_h2 [TT*CC];        // LN2 output
__device__ float g_fc [TT*4*CC];      // GELU(fc)

// ---------------- edge table precompute: EK/EV = edge_emb @ W^T + b ----------
__global__ void edge_pre(const float* __restrict__ emb,
                         const float* __restrict__ Wk, const float* __restrict__ bk,
                         const float* __restrict__ Wv, const float* __restrict__ bv,
                         float* __restrict__ EK, float* __restrict__ EV) {
    int e = blockIdx.x;           // 16 blocks
    int n = threadIdx.x;          // 512 threads
    __shared__ float er[CC];
    er[n] = emb[e*CC + n];
    __syncthreads();
    const float4* wk = (const float4*)(Wk + n*CC);
    const float4* wv = (const float4*)(Wv + n*CC);
    float sk = 0.f, sv = 0.f;
    #pragma unroll 4
    for (int k = 0; k < CC/4; k++) {
        float4 a = wk[k], b = wv[k];
        float e0 = er[4*k+0], e1 = er[4*k+1], e2 = er[4*k+2], e3 = er[4*k+3];
        sk = fmaf(e0,a.x, fmaf(e1,a.y, fmaf(e2,a.z, fmaf(e3,a.w, sk))));
        sv = fmaf(e0,b.x, fmaf(e1,b.y, fmaf(e2,b.z, fmaf(e3,b.w, sv))));
    }
    EK[e*CC + n] = sk + bk[n];
    EV[e*CC + n] = sv + bv[n];
}

// ---------------- layernorm (row of 512, 256 threads/row) -------------------
__global__ void ln_kernel(const float* __restrict__ x, const float* __restrict__ w,
                          const float* __restrict__ b, float* __restrict__ out) {
    int row = blockIdx.x;
    int tid = threadIdx.x;                 // 256
    int lane = tid & 31, wid = tid >> 5;
    const float* xr = x + row*CC;
    float v0 = xr[tid], v1 = xr[tid + 256];

    __shared__ float rbuf[8];
    __shared__ float stats[2];

    float s = v0 + v1;
    #pragma unroll
    for (int o = 16; o > 0; o >>= 1) s += __shfl_xor_sync(0xffffffffu, s, o);
    if (lane == 0) rbuf[wid] = s;
    __syncthreads();
    if (tid == 0) {
        float t = 0.f;
        #pragma unroll
        for (int i = 0; i < 8; i++) t += rbuf[i];
        stats[0] = t * (1.0f/CC);
    }
    __syncthreads();
    float mu = stats[0];
    float d0 = v0 - mu, d1 = v1 - mu;
    float q = d0*d0 + d1*d1;
    #pragma unroll
    for (int o = 16; o > 0; o >>= 1) q += __shfl_xor_sync(0xffffffffu, q, o);
    if (lane == 0) rbuf[wid] = q;
    __syncthreads();
    if (tid == 0) {
        float t = 0.f;
        #pragma unroll
        for (int i = 0; i < 8; i++) t += rbuf[i];
        stats[1] = rsqrtf(t * (1.0f/CC) + 1e-5f);
    }
    __syncthreads();
    float rstd = stats[1];
    out[row*CC + tid]       = d0 * rstd * w[tid]       + b[tid];
    out[row*CC + tid + 256] = d1 * rstd * w[tid + 256] + b[tid + 256];
}

// ---------------- tf32 tensor-core NT GEMM (round-4 proven version) ----------
// C[m,n] = sum_k A[m,k]*B[n,k] + bias[n] ; EPI: 0=bias, 1=bias+res, 2=bias+GELU
// BM=BN=64, BK=32, 128 threads (4 warps in 2x2), warp tile 32x32 (2x4 mma m16n8k8)
__device__ __forceinline__ void mma_tf32(float c[4], const uint32_t a[4], const uint32_t b[2]) {
    asm volatile(
        "mma.sync.aligned.m16n8k8.row.col.f32.tf32.tf32.f32 "
        "{%0,%1,%2,%3}, {%4,%5,%6,%7}, {%8,%9}, {%0,%1,%2,%3};\n"
        : "+f"(c[0]), "+f"(c[1]), "+f"(c[2]), "+f"(c[3])
        : "r"(a[0]), "r"(a[1]), "r"(a[2]), "r"(a[3]), "r"(b[0]), "r"(b[1]));
}
__device__ __forceinline__ uint32_t f2tf32(float x) {
    uint32_t r;
    asm("cvt.rna.tf32.f32 %0, %1;\n" : "=r"(r) : "f"(x));
    return r;
}
__device__ __forceinline__ float epi_apply(float v, float r, int EPI) {
    if (EPI == 1) v += r;
    if (EPI == 2) v = 0.5f * v * (1.0f + erff(v * 0.70710678118654752f));
    return v;
}

template<int EPI>
__global__ void gemm_tc(const float* __restrict__ A, const float* __restrict__ B,
                        const float* __restrict__ bias, const float* __restrict__ res,
                        float* __restrict__ Cout, int M, int N, int K) {
    __shared__ uint32_t As[64][36];
    __shared__ uint32_t Bs[64][36];
    int tid = threadIdx.x;            // 128
    int warp = tid >> 5, lane = tid & 31;
    int wm = warp & 1, wn = warp >> 1;        // 2 x 2 warps
    int bm = blockIdx.y * 64, bn = blockIdx.x * 64;
    int lr = tid >> 3;                // 0..15 (row within 16-row slab)
    int lc = tid & 7;                 // 0..7  (float4 column)

    const float* Ap = A + (size_t)(bm + lr)*K + lc*4;
    const float* Bp = B + (size_t)(bn + lr)*K + lc*4;

    float acc[2][4][4] = {};

    for (int k0 = 0; k0 < K; k0 += 32) {
        #pragma unroll
        for (int rr = 0; rr < 4; rr++) {
            float4 a = *(const float4*)(Ap + (size_t)(rr*16)*K + k0);
            float4 b = *(const float4*)(Bp + (size_t)(rr*16)*K + k0);
            uint4 at = make_uint4(f2tf32(a.x), f2tf32(a.y), f2tf32(a.z), f2tf32(a.w));
            uint4 bt = make_uint4(f2tf32(b.x), f2tf32(b.y), f2tf32(b.z), f2tf32(b.w));
            *(uint4*)&As[lr + 16*rr][lc*4] = at;
            *(uint4*)&Bs[lr + 16*rr][lc*4] = bt;
        }
        __syncthreads();
        #pragma unroll
        for (int ko = 0; ko < 32; ko += 8) {
            uint32_t af[2][4], bf[4][2];
            int qr = lane >> 2, qc = lane & 3;
            #pragma unroll
            for (int mi = 0; mi < 2; mi++) {
                int row = wm*32 + mi*16 + qr;
                af[mi][0] = As[row    ][ko + qc];
                af[mi][1] = As[row + 8][ko + qc];
                af[mi][2] = As[row    ][ko + 4 + qc];
                af[mi][3] = As[row + 8][ko + 4 + qc];
            }
            #pragma unroll
            for (int ni = 0; ni < 4; ni++) {
                int col = wn*32 + ni*8 + qr;
                bf[ni][0] = Bs[col][ko + qc];
                bf[ni][1] = Bs[col][ko + 4 + qc];
            }
            #pragma unroll
            for (int mi = 0; mi < 2; mi++)
                #pragma unroll
                for (int ni = 0; ni < 4; ni++)
                    mma_tf32(acc[mi][ni], af[mi], bf[ni]);
        }
        __syncthreads();
    }

    // epilogue
    int qr = lane >> 2, qc = lane & 3;
    #pragma unroll
    for (int mi = 0; mi < 2; mi++) {
        int row0 = bm + wm*32 + mi*16 + qr;
        #pragma unroll
        for (int ni = 0; ni < 4; ni++) {
            int col = bn + wn*32 + ni*8 + qc*2;
            float b0 = bias[col], b1 = bias[col + 1];
            float* cp0 = Cout + (size_t)row0*N + col;
            float* cp1 = Cout + (size_t)(row0 + 8)*N + col;
            float r00 = 0.f, r01 = 0.f, r10 = 0.f, r11 = 0.f;
            if (EPI == 1) {
                const float* rp0 = res + (size_t)row0*N + col;
                const float* rp1 = res + (size_t)(row0 + 8)*N + col;
                r00 = rp0[0]; r01 = rp0[1]; r10 = rp1[0]; r11 = rp1[1];
            }
            float2 o0, o1;
            o0.x = epi_apply(acc[mi][ni][0] + b0, r00, EPI);
            o0.y = epi_apply(acc[mi][ni][1] + b1, r01, EPI);
            o1.x = epi_apply(acc[mi][ni][2] + b0, r10, EPI);
            o1.y = epi_apply(acc[mi][ni][3] + b1, r11, EPI);
            *(float2*)cp0 = o0;
            *(float2*)cp1 = o1;
        }
    }
}

// ---------------- gather attention v3: block per i, all heads ----------------
// 256 threads = 8 warps.
// pass1: warp per j; lanes split C=512 (float4), coalesced K + L1-resident EK.
// pass2: warp per head; lanes = (j-half, d4), coalesced V + L1-resident EV.
__global__ void __launch_bounds__(256)
attn3(const float* __restrict__ qkv, const int* __restrict__ bm,
      const float* __restrict__ EK, const float* __restrict__ EV,
      const float* __restrict__ abe, float* __restrict__ y) {
    int b = blockIdx.x;
    int i = (b & 1) ? (b >> 1) : (TT - 1 - (b >> 1));   // pair big+small i
    int tid = threadIdx.x;
    int lane = tid & 31, wid = tid >> 5;

    __shared__ float4 q_s[CC/4];          // q row, float4
    __shared__ float  s_s[HH][TT];        // scores -> probs
    __shared__ int    e_s[TT];
    __shared__ float  ab_s[EE][HH];

    if (tid < CC/4) q_s[tid] = ((const float4*)(qkv + (size_t)i*3*CC))[tid];
    if (tid < EE*HH) ab_s[tid >> 3][tid & 7] = abe[tid];
    for (int j = tid; j <= i; j += 256) e_s[j] = bm[i*TT + j];
    __syncthreads();

    const float4* EK4 = (const float4*)EK;
    const float4* EV4 = (const float4*)EV;
    const float4* qkv4 = (const float4*)qkv;

    // ---- pass 1: warp w handles j = w, w+8, ... ----
    for (int j = wid; j <= i; j += 8) {
        int e = e_s[j];
        const float4* k4 = qkv4 + ((size_t)j*3*CC + CC)/4;
        const float4* ek = EK4 + e*(CC/4);
        float sr[4];
        #pragma unroll
        for (int r = 0; r < 4; r++) {
            int c4 = lane + 32*r;
            float4 kk = k4[c4];
            float4 ee = ek[c4];
            float4 qq = q_s[c4];
            float s = qq.x * (kk.x * ee.x);
            s = fmaf(qq.y, kk.y * ee.y, s);
            s = fmaf(qq.z, kk.z * ee.z, s);
            s = fmaf(qq.w, kk.w * ee.w, s);
            sr[r] = s;
        }
        // reduce within 16-lane groups (head = (lane>>4) + 2r)
        #pragma unroll
        for (int r = 0; r < 4; r++) {
            #pragma unroll
            for (int o = 8; o >= 1; o >>= 1)
                sr[r] += __shfl_xor_sync(0xffffffffu, sr[r], o);
        }
        if ((lane & 15) == 0) {
            int hb = lane >> 4;          // 0 or 1
            #pragma unroll
            for (int r = 0; r < 4; r++) {
                int h = 2*r + hb;
                s_s[h][j] = sr[r] * 0.125f + ab_s[e][h];
            }
        }
    }
    __syncthreads();

    // ---- softmax: warp = head (stats stay in registers) ----
    int h = wid;
    float lm = -1e30f;
    for (int j = lane; j <= i; j += 32) lm = fmaxf(lm, s_s[h][j]);
    #pragma unroll
    for (int o = 16; o > 0; o >>= 1) lm = fmaxf(lm, __shfl_xor_sync(0xffffffffu, lm, o));
    float ls = 0.f;
    for (int j = lane; j <= i; j += 32) {
        float p = __expf(s_s[h][j] - lm);
        s_s[h][j] = p;
        ls += p;
    }
    #pragma unroll
    for (int o = 16; o > 0; o >>= 1) ls += __shfl_xor_sync(0xffffffffu, ls, o);
    float inv = 1.0f / ls;

    // ---- pass 2: warp = head; lane = (half, d4) ----
    int half = lane >> 4, d4 = lane & 15;
    float4 acc = make_float4(0.f, 0.f, 0.f, 0.f);
    for (int j = half; j <= i; j += 2) {
        float p = s_s[h][j];
        int e = e_s[j];
        float4 vv = qkv4[((size_t)j*3*CC + 2*CC)/4 + h*16 + d4];
        float4 ev = EV4[e*(CC/4) + h*16 + d4];
        acc.x = fmaf(p, vv.x * ev.x, acc.x);
        acc.y = fmaf(p, vv.y * ev.y, acc.y);
        acc.z = fmaf(p, vv.z * ev.z, acc.z);
        acc.w = fmaf(p, vv.w * ev.w, acc.w);
    }
    acc.x += __shfl_xor_sync(0xffffffffu, acc.x, 16);
    acc.y += __shfl_xor_sync(0xffffffffu, acc.y, 16);
    acc.z += __shfl_xor_sync(0xffffffffu, acc.z, 16);
    acc.w += __shfl_xor_sync(0xffffffffu, acc.w, 16);
    if (half == 0) {
        float4 o = make_float4(acc.x*inv, acc.y*inv, acc.z*inv, acc.w*inv);
        ((float4*)(y + (size_t)i*CC + h*DD))[d4] = o;
    }
}

// ---------------- host launch ------------------------------------------------
extern "C" void kernel_launch(void* const* d_in, const int* in_sizes, int n_in,
                              void* d_out, int out_size) {
    const float* x        = (const float*)d_in[0];
    const int*   bmx      = (const int*)  d_in[1];
    const float* ln1_w    = (const float*)d_in[2];
    const float* ln1_b    = (const float*)d_in[3];
    const float* w_attn_w = (const float*)d_in[4];
    const float* w_attn_b = (const float*)d_in[5];
    const float* w_proj_w = (const float*)d_in[6];
    const float* w_proj_b = (const float*)d_in[7];
    const float* abe      = (const float*)d_in[8];
    const float* edge_emb = (const float*)d_in[9];
    const float* wek      = (const float*)d_in[10];
    const float* bek      = (const float*)d_in[11];
    const float* wev      = (const float*)d_in[12];
    const float* bev      = (const float*)d_in[13];
    const float* ln2_w    = (const float*)d_in[14];
    const float* ln2_b    = (const float*)d_in[15];
    const float* c_fc_w   = (const float*)d_in[16];
    const float* c_fc_b   = (const float*)d_in[17];
    const float* c_proj_w = (const float*)d_in[18];
    const float* c_proj_b = (const float*)d_in[19];
    float* out = (float*)d_out;

    float *pH, *pQKV, *pEK, *pEV, *pY, *pX1, *pH2, *pFC;
    cudaGetSymbolAddress((void**)&pH,   g_h);
    cudaGetSymbolAddress((void**)&pQKV, g_qkv);
    cudaGetSymbolAddress((void**)&pEK,  g_EK);
    cudaGetSymbolAddress((void**)&pEV,  g_EV);
    cudaGetSymbolAddress((void**)&pY,   g_y);
    cudaGetSymbolAddress((void**)&pX1,  g_x1);
    cudaGetSymbolAddress((void**)&pH2,  g_h2);
    cudaGetSymbolAddress((void**)&pFC,  g_fc);

    // 1. edge tables
    edge_pre<<<EE, CC>>>(edge_emb, wek, bek, wev, bev, pEK, pEV);
    // 2. LN1
    ln_kernel<<<TT, 256>>>(x, ln1_w, ln1_b, pH);
    // 3. QKV = LN1 @ w_attn^T + b   (384 x 1536 x 512)
    gemm_tc<0><<<dim3(3*CC/64, TT/64), 128>>>(pH, w_attn_w, w_attn_b, nullptr, pQKV, TT, 3*CC, CC);
    // 4. gather attention (block per i)
    attn3<<<TT, 256>>>(pQKV, bmx, pEK, pEV, abe, pY);
    // 5. x1 = x + y @ w_proj^T + b  (384 x 512 x 512)
    gemm_tc<1><<<dim3(CC/64, TT/64), 128>>>(pY, w_proj_w, w_proj_b, x, pX1, TT, CC, CC);
    // 6. LN2
    ln_kernel<<<TT, 256>>>(pX1, ln2_w, ln2_b, pH2);
    // 7. fc = gelu(h2 @ c_fc^T + b) (384 x 2048 x 512)
    gemm_tc<2><<<dim3(4*CC/64, TT/64), 128>>>(pH2, c_fc_w, c_fc_b, nullptr, pFC, TT, 4*CC, CC);
    // 8. out = x1 + fc @ c_proj^T + b (384 x 512 x 2048)
    gemm_tc<1><<<dim3(CC/64, TT/64), 128>>>(pFC, c_proj_w, c_proj_b, pX1, out, TT, CC, 4*CC);
}

// round 9
// speedup vs baseline: 1.6147x; 1.5696x over previous
#include <cuda_runtime.h>
#include <math.h>
#include <stdint.h>

#define TT 384
#define CC 512
#define HH 8
#define DD 64
#define EE 16

// ---------------- scratch (device globals; no allocs allowed) ----------------
__device__ float g_h  [TT*CC];        // LN1 output
__device__ float g_qkv[TT*3*CC];      // QKV
__device__ float g_EV [EE*CC];        // edge-v table [e][c]
__device__ float g_EKt[CC*EE];        // edge-k table transposed [c][e]
__device__ float g_Kt [CC*TT];        // K transposed: [c][j]
__device__ float g_y  [TT*CC];        // attention output (pre-proj)
__device__ float g_x1 [TT*CC];        // x + attn
__device__ float g_h2 [TT*CC];        // LN2 output
__device__ float g_fc [TT*4*CC];      // GELU(fc)

// ---------------- cp.async helpers ------------------------------------------
__device__ __forceinline__ void cp16(void* smem, const void* gmem) {
    uint32_t s = (uint32_t)__cvta_generic_to_shared(smem);
    asm volatile("cp.async.cg.shared.global [%0], [%1], 16;\n" :: "r"(s), "l"(gmem));
}
__device__ __forceinline__ void cp_commit() {
    asm volatile("cp.async.commit_group;\n");
}
template<int N>
__device__ __forceinline__ void cp_wait() {
    asm volatile("cp.async.wait_group %0;\n" :: "n"(N));
}

// ---------------- edge table precompute: EKt/EV = edge_emb @ W^T + b ---------
__global__ void edge_pre(const float* __restrict__ emb,
                         const float* __restrict__ Wk, const float* __restrict__ bk,
                         const float* __restrict__ Wv, const float* __restrict__ bv,
                         float* __restrict__ EKt, float* __restrict__ EV) {
    int e = blockIdx.x;           // 16 blocks
    int n = threadIdx.x;          // 512 threads
    __shared__ float er[CC];
    er[n] = emb[e*CC + n];
    __syncthreads();
    const float4* wk = (const float4*)(Wk + n*CC);
    const float4* wv = (const float4*)(Wv + n*CC);
    float sk = 0.f, sv = 0.f;
    #pragma unroll 4
    for (int k = 0; k < CC/4; k++) {
        float4 a = wk[k], b = wv[k];
        float e0 = er[4*k+0], e1 = er[4*k+1], e2 = er[4*k+2], e3 = er[4*k+3];
        sk = fmaf(e0,a.x, fmaf(e1,a.y, fmaf(e2,a.z, fmaf(e3,a.w, sk))));
        sv = fmaf(e0,b.x, fmaf(e1,b.y, fmaf(e2,b.z, fmaf(e3,b.w, sv))));
    }
    EKt[n*EE + e] = sk + bk[n];
    EV [e*CC + n] = sv + bv[n];
}

// ---------------- layernorm (row of 512, 256 threads/row) -------------------
__global__ void ln_kernel(const float* __restrict__ x, const float* __restrict__ w,
                          const float* __restrict__ b, float* __restrict__ out) {
    int row = blockIdx.x;
    int tid = threadIdx.x;                 // 256
    int lane = tid & 31, wid = tid >> 5;
    const float* xr = x + row*CC;
    float v0 = xr[tid], v1 = xr[tid + 256];

    __shared__ float rbuf[8];
    __shared__ float stats[2];

    float s = v0 + v1;
    #pragma unroll
    for (int o = 16; o > 0; o >>= 1) s += __shfl_xor_sync(0xffffffffu, s, o);
    if (lane == 0) rbuf[wid] = s;
    __syncthreads();
    if (tid == 0) {
        float t = 0.f;
        #pragma unroll
        for (int i = 0; i < 8; i++) t += rbuf[i];
        stats[0] = t * (1.0f/CC);
    }
    __syncthreads();
    float mu = stats[0];
    float d0 = v0 - mu, d1 = v1 - mu;
    float q = d0*d0 + d1*d1;
    #pragma unroll
    for (int o = 16; o > 0; o >>= 1) q += __shfl_xor_sync(0xffffffffu, q, o);
    if (lane == 0) rbuf[wid] = q;
    __syncthreads();
    if (tid == 0) {
        float t = 0.f;
        #pragma unroll
        for (int i = 0; i < 8; i++) t += rbuf[i];
        stats[1] = rsqrtf(t * (1.0f/CC) + 1e-5f);
    }
    __syncthreads();
    float rstd = stats[1];
    out[row*CC + tid]       = d0 * rstd * w[tid]       + b[tid];
    out[row*CC + tid + 256] = d1 * rstd * w[tid + 256] + b[tid + 256];
}

// ---------------- tf32 tensor-core NT GEMM, cp.async 3-stage, no cvt ---------
// C[m,n] = sum_k A[m,k]*B[n,k] + bias[n] ; EPI: 0=bias, 1=bias+res, 2=bias+GELU
// fp32 operands fed directly to mma.tf32 (implicit truncation; rel_err budget OK)
__device__ __forceinline__ void mma_tf32(float c[4], const uint32_t a[4], const uint32_t b[2]) {
    asm volatile(
        "mma.sync.aligned.m16n8k8.row.col.f32.tf32.tf32.f32 "
        "{%0,%1,%2,%3}, {%4,%5,%6,%7}, {%8,%9}, {%0,%1,%2,%3};\n"
        : "+f"(c[0]), "+f"(c[1]), "+f"(c[2]), "+f"(c[3])
        : "r"(a[0]), "r"(a[1]), "r"(a[2]), "r"(a[3]), "r"(b[0]), "r"(b[1]));
}
__device__ __forceinline__ float epi_apply(float v, float r, int EPI) {
    if (EPI == 1) v += r;
    if (EPI == 2) v = 0.5f * v * (1.0f + erff(v * 0.70710678118654752f));
    return v;
}

// BM in {32,64}, BN=64, BK=32, 128 threads (4 warps, 2x2), 3-stage cp.async
template<int BM, int EPI, bool WKT>
__global__ void __launch_bounds__(128)
gemm_pl(const float* __restrict__ A, const float* __restrict__ B,
        const float* __restrict__ bias, const float* __restrict__ res,
        float* __restrict__ Cout, float* __restrict__ Kt,
        int M, int N, int K) {
    constexpr int BN = 64, PAD = 36;
    constexpr int MI = BM / 32;              // m16 frags per warp (2 or 1)
    constexpr int NI = 4;                    // n8 frags per warp (warp n-width 32)
    constexpr int CA = BM * 8 / 128;         // float4 chunks per thread (A)
    constexpr int CB = BN * 8 / 128;         // (B) = 4

    extern __shared__ float sm[];
    float* As = sm;                          // [3][BM][PAD]
    float* Bs = sm + 3*BM*PAD;               // [3][BN][PAD]

    int tid = threadIdx.x;
    int warp = tid >> 5, lane = tid & 31;
    int wm = warp & 1, wn = warp >> 1;       // 2x2
    int qr = lane >> 2, qc = lane & 3;
    int bm = blockIdx.y * BM, bn = blockIdx.x * BN;
    const int KT = K >> 5;

    float acc[MI][NI][4] = {};

    auto loadtile = [&](int st, int k0) {
        #pragma unroll
        for (int c = 0; c < CA; c++) {
            int ch = tid + c*128;
            int r = ch >> 3, c4 = (ch & 7) << 2;
            cp16(&As[(st*BM + r)*PAD + c4], A + (size_t)(bm + r)*K + k0 + c4);
        }
        #pragma unroll
        for (int c = 0; c < CB; c++) {
            int ch = tid + c*128;
            int r = ch >> 3, c4 = (ch & 7) << 2;
            cp16(&Bs[(st*BN + r)*PAD + c4], B + (size_t)(bn + r)*K + k0 + c4);
        }
    };

    loadtile(0, 0);  cp_commit();
    loadtile(1, 32); cp_commit();

    for (int kt = 0; kt < KT; kt++) {
        cp_wait<1>();
        __syncthreads();
        if (kt + 2 < KT) loadtile((kt + 2) % 3, (kt + 2) << 5);
        cp_commit();
        int st = kt % 3;
        const float* as = As + st*BM*PAD;
        const float* bs = Bs + st*BN*PAD;
        #pragma unroll
        for (int ko = 0; ko < 32; ko += 8) {
            uint32_t af[MI][4], bf[NI][2];
            #pragma unroll
            for (int mi = 0; mi < MI; mi++) {
                int row = wm*(MI*16) + mi*16 + qr;
                af[mi][0] = __float_as_uint(as[(row    )*PAD + ko + qc]);
                af[mi][1] = __float_as_uint(as[(row + 8)*PAD + ko + qc]);
                af[mi][2] = __float_as_uint(as[(row    )*PAD + ko + 4 + qc]);
                af[mi][3] = __float_as_uint(as[(row + 8)*PAD + ko + 4 + qc]);
            }
            #pragma unroll
            for (int ni = 0; ni < NI; ni++) {
                int col = wn*32 + ni*8 + qr;
                bf[ni][0] = __float_as_uint(bs[col*PAD + ko + qc]);
                bf[ni][1] = __float_as_uint(bs[col*PAD + ko + 4 + qc]);
            }
            #pragma unroll
            for (int mi = 0; mi < MI; mi++)
                #pragma unroll
                for (int ni = 0; ni < NI; ni++)
                    mma_tf32(acc[mi][ni], af[mi], bf[ni]);
        }
        __syncthreads();
    }

    // epilogue
    #pragma unroll
    for (int mi = 0; mi < MI; mi++) {
        int row0 = bm + wm*(MI*16) + mi*16 + qr;
        #pragma unroll
        for (int ni = 0; ni < NI; ni++) {
            int col = bn + wn*32 + ni*8 + qc*2;
            float b0 = bias[col], b1 = bias[col + 1];
            float* cp0 = Cout + (size_t)row0*N + col;
            float* cp1 = Cout + (size_t)(row0 + 8)*N + col;
            float r00 = 0.f, r01 = 0.f, r10 = 0.f, r11 = 0.f;
            if (EPI == 1) {
                const float* rp0 = res + (size_t)row0*N + col;
                const float* rp1 = res + (size_t)(row0 + 8)*N + col;
                r00 = rp0[0]; r01 = rp0[1]; r10 = rp1[0]; r11 = rp1[1];
            }
            float2 o0, o1;
            o0.x = epi_apply(acc[mi][ni][0] + b0, r00, EPI);
            o0.y = epi_apply(acc[mi][ni][1] + b1, r01, EPI);
            o1.x = epi_apply(acc[mi][ni][2] + b0, r10, EPI);
            o1.y = epi_apply(acc[mi][ni][3] + b1, r11, EPI);
            *(float2*)cp0 = o0;
            *(float2*)cp1 = o1;
            if (WKT && col >= CC && col < 2*CC) {   // fused K transpose
                int kc = col - CC;
                Kt[(size_t)kc*TT + row0]           = o0.x;
                Kt[(size_t)(kc + 1)*TT + row0]     = o0.y;
                Kt[(size_t)kc*TT + row0 + 8]       = o1.x;
                Kt[(size_t)(kc + 1)*TT + row0 + 8] = o1.y;
            }
        }
    }
}

// ---------------- gather attention (R4-proven): block per (i,h), 128 thr -----
__global__ void attn2(const float* __restrict__ qkv, const float* __restrict__ Kt,
                      const int* __restrict__ bm,
                      const float* __restrict__ EKt, const float* __restrict__ EV,
                      const float* __restrict__ abe, float* __restrict__ y) {
    int i = TT - 1 - blockIdx.x;          // heavy blocks first
    int h = blockIdx.y;
    int tid = threadIdx.x;                // 128
    int lane = tid & 31, wid = tid >> 5;

    __shared__ float qe_s[DD*EE];         // [d][e] = q[d]*EK[e][d]
    __shared__ float EV_s[EE*DD];         // [e][d]
    __shared__ float ab_s[EE];
    __shared__ float s_s[TT];
    __shared__ int   e_s[TT];
    __shared__ float psum[2][DD];
    __shared__ float rbuf[4];
    __shared__ float resv[2];

    const float* EKh = EKt + h*DD*EE;
    #pragma unroll
    for (int k = 0; k < 8; k++) {         // 1024 / 128
        int idx = tid + k*128;
        int d = idx >> 4;
        qe_s[idx] = qkv[(size_t)i*3*CC + h*DD + d] * EKh[idx];
        EV_s[idx] = EV[(size_t)(idx >> 6)*CC + h*DD + (idx & 63)];
    }
    if (tid < EE) ab_s[tid] = abe[tid*HH + h];
    __syncthreads();

    // pass 1: thread-per-j dot products against transposed K
    const float* KtH = Kt + (size_t)h*DD*TT;
    for (int j = tid; j <= i; j += 128) {
        int e = bm[i*TT + j];
        const float* kp = KtH + j;
        float s = 0.f;
        #pragma unroll 16
        for (int d = 0; d < DD; d++)
            s = fmaf(qe_s[d*EE + e], kp[(size_t)d*TT], s);
        s_s[j] = s * 0.125f + ab_s[e];
        e_s[j] = e;
    }
    __syncthreads();

    // block max
    float lm = -1e30f;
    for (int j = tid; j <= i; j += 128) lm = fmaxf(lm, s_s[j]);
    #pragma unroll
    for (int o = 16; o > 0; o >>= 1) lm = fmaxf(lm, __shfl_xor_sync(0xffffffffu, lm, o));
    if (lane == 0) rbuf[wid] = lm;
    __syncthreads();
    if (tid == 0) resv[0] = fmaxf(fmaxf(rbuf[0], rbuf[1]), fmaxf(rbuf[2], rbuf[3]));
    __syncthreads();
    float m = resv[0];

    // exp + sum
    float ls = 0.f;
    for (int j = tid; j <= i; j += 128) {
        float p = __expf(s_s[j] - m);
        s_s[j] = p;
        ls += p;
    }
    #pragma unroll
    for (int o = 16; o > 0; o >>= 1) ls += __shfl_xor_sync(0xffffffffu, ls, o);
    if (lane == 0) rbuf[wid] = ls;
    __syncthreads();
    if (tid == 0) resv[1] = 1.0f / (rbuf[0] + rbuf[1] + rbuf[2] + rbuf[3]);
    __syncthreads();
    float inv = resv[1];

    // pass 2: weighted V accumulate
    int d = tid & 63, half = tid >> 6;
    float acc = 0.f;
    for (int j = half; j <= i; j += 2) {
        int e = e_s[j];
        acc = fmaf(s_s[j], qkv[(size_t)j*3*CC + 2*CC + h*DD + d] * EV_s[e*DD + d], acc);
    }
    psum[half][d] = acc;
    __syncthreads();
    if (tid < DD) y[(size_t)i*CC + h*DD + tid] = (psum[0][tid] + psum[1][tid]) * inv;
}

// ---------------- host launch ------------------------------------------------
extern "C" void kernel_launch(void* const* d_in, const int* in_sizes, int n_in,
                              void* d_out, int out_size) {
    const float* x        = (const float*)d_in[0];
    const int*   bmx      = (const int*)  d_in[1];
    const float* ln1_w    = (const float*)d_in[2];
    const float* ln1_b    = (const float*)d_in[3];
    const float* w_attn_w = (const float*)d_in[4];
    const float* w_attn_b = (const float*)d_in[5];
    const float* w_proj_w = (const float*)d_in[6];
    const float* w_proj_b = (const float*)d_in[7];
    const float* abe      = (const float*)d_in[8];
    const float* edge_emb = (const float*)d_in[9];
    const float* wek      = (const float*)d_in[10];
    const float* bek      = (const float*)d_in[11];
    const float* wev      = (const float*)d_in[12];
    const float* bev      = (const float*)d_in[13];
    const float* ln2_w    = (const float*)d_in[14];
    const float* ln2_b    = (const float*)d_in[15];
    const float* c_fc_w   = (const float*)d_in[16];
    const float* c_fc_b   = (const float*)d_in[17];
    const float* c_proj_w = (const float*)d_in[18];
    const float* c_proj_b = (const float*)d_in[19];
    float* out = (float*)d_out;

    float *pH, *pQKV, *pEKt, *pEV, *pKt, *pY, *pX1, *pH2, *pFC;
    cudaGetSymbolAddress((void**)&pH,   g_h);
    cudaGetSymbolAddress((void**)&pQKV, g_qkv);
    cudaGetSymbolAddress((void**)&pEKt, g_EKt);
    cudaGetSymbolAddress((void**)&pEV,  g_EV);
    cudaGetSymbolAddress((void**)&pKt,  g_Kt);
    cudaGetSymbolAddress((void**)&pY,   g_y);
    cudaGetSymbolAddress((void**)&pX1,  g_x1);
    cudaGetSymbolAddress((void**)&pH2,  g_h2);
    cudaGetSymbolAddress((void**)&pFC,  g_fc);

    constexpr int SM64 = 3*(64 + 64)*36*4;   // 55296 B
    constexpr int SM32 = 3*(32 + 64)*36*4;   // 41472 B
    static int attr_done = 0;
    if (!attr_done) {
        cudaFuncSetAttribute(gemm_pl<64,0,true >, cudaFuncAttributeMaxDynamicSharedMemorySize, SM64);
        cudaFuncSetAttribute(gemm_pl<64,2,false>, cudaFuncAttributeMaxDynamicSharedMemorySize, SM64);
        cudaFuncSetAttribute(gemm_pl<32,1,false>, cudaFuncAttributeMaxDynamicSharedMemorySize, SM32);
        attr_done = 1;
    }

    // 1. edge tables
    edge_pre<<<EE, CC>>>(edge_emb, wek, bek, wev, bev, pEKt, pEV);
    // 2. LN1
    ln_kernel<<<TT, 256>>>(x, ln1_w, ln1_b, pH);
    // 3. QKV = LN1 @ w_attn^T + b (384 x 1536 x 512), fused K-transpose
    gemm_pl<64,0,true><<<dim3(3*CC/64, TT/64), 128, SM64>>>(pH, w_attn_w, w_attn_b, nullptr, pQKV, pKt, TT, 3*CC, CC);
    // 4. gather attention
    attn2<<<dim3(TT, HH), 128>>>(pQKV, pKt, bmx, pEKt, pEV, abe, pY);
    // 5. x1 = x + y @ w_proj^T + b (384 x 512 x 512)
    gemm_pl<32,1,false><<<dim3(CC/64, TT/32), 128, SM32>>>(pY, w_proj_w, w_proj_b, x, pX1, nullptr, TT, CC, CC);
    // 6. LN2
    ln_kernel<<<TT, 256>>>(pX1, ln2_w, ln2_b, pH2);
    // 7. fc = gelu(h2 @ c_fc^T + b) (384 x 2048 x 512)
    gemm_pl<64,2,false><<<dim3(4*CC/64, TT/64), 128, SM64>>>(pH2, c_fc_w, c_fc_b, nullptr, pFC, nullptr, TT, 4*CC, CC);
    // 8. out = x1 + fc @ c_proj^T + b (384 x 512 x 2048)
    gemm_pl<32,1,false><<<dim3(CC/64, TT/32), 128, SM32>>>(pFC, c_proj_w, c_proj_b, pX1, out, nullptr, TT, CC, 4*CC);
}

// round 12
// speedup vs baseline: 1.6944x; 1.0494x over previous
#include <cuda_runtime.h>
#include <math.h>
#include <stdint.h>

#define TT 384
#define CC 512
#define HH 8
#define DD 64
#define EE 16

// ---------------- scratch (device globals; no allocs allowed) ----------------
__device__ float g_h   [TT*CC];       // LN1 output
__device__ float g_qkv [TT*3*CC];     // QKV
__device__ float g_EV  [EE*CC];       // edge-v table [e][c]
__device__ float g_EKt [CC*EE];       // edge-k table transposed [c][e]
__device__ float g_Kt  [CC*TT];       // K transposed: [c][j]
__device__ float g_y   [TT*CC];       // attention output (pre-proj)
__device__ float g_x1  [TT*CC];       // x + attn
__device__ float g_h2  [TT*CC];       // LN2 output
__device__ float g_fc  [TT*4*CC];     // GELU(fc)
__device__ float g_part[4*TT*CC];     // split-K partials

// ---------------- cp.async helpers ------------------------------------------
__device__ __forceinline__ void cp16(void* smem, const void* gmem) {
    uint32_t s = (uint32_t)__cvta_generic_to_shared(smem);
    asm volatile("cp.async.cg.shared.global [%0], [%1], 16;\n" :: "r"(s), "l"(gmem));
}
__device__ __forceinline__ void cp_commit() {
    asm volatile("cp.async.commit_group;\n");
}
template<int N>
__device__ __forceinline__ void cp_wait() {
    asm volatile("cp.async.wait_group %0;\n" :: "n"(N));
}

// ---------------- edge table precompute: EKt/EV = edge_emb @ W^T + b ---------
__global__ void edge_pre(const float* __restrict__ emb,
                         const float* __restrict__ Wk, const float* __restrict__ bk,
                         const float* __restrict__ Wv, const float* __restrict__ bv,
                         float* __restrict__ EKt, float* __restrict__ EV) {
    int e = blockIdx.x;           // 16 blocks
    int n = threadIdx.x;          // 512 threads
    __shared__ float er[CC];
    er[n] = emb[e*CC + n];
    __syncthreads();
    const float4* wk = (const float4*)(Wk + n*CC);
    const float4* wv = (const float4*)(Wv + n*CC);
    float sk = 0.f, sv = 0.f;
    #pragma unroll 4
    for (int k = 0; k < CC/4; k++) {
        float4 a = wk[k], b = wv[k];
        float e0 = er[4*k+0], e1 = er[4*k+1], e2 = er[4*k+2], e3 = er[4*k+3];
        sk = fmaf(e0,a.x, fmaf(e1,a.y, fmaf(e2,a.z, fmaf(e3,a.w, sk))));
        sv = fmaf(e0,b.x, fmaf(e1,b.y, fmaf(e2,b.z, fmaf(e3,b.w, sv))));
    }
    EKt[n*EE + e] = sk + bk[n];
    EV [e*CC + n] = sv + bv[n];
}

// ---------------- layernorm (row of 512, 256 threads/row) -------------------
__global__ void ln_kernel(const float* __restrict__ x, const float* __restrict__ w,
                          const float* __restrict__ b, float* __restrict__ out) {
    int row = blockIdx.x;
    int tid = threadIdx.x;                 // 256
    int lane = tid & 31, wid = tid >> 5;
    const float* xr = x + row*CC;
    float v0 = xr[tid], v1 = xr[tid + 256];

    __shared__ float rbuf[8];
    __shared__ float stats[2];

    float s = v0 + v1;
    #pragma unroll
    for (int o = 16; o > 0; o >>= 1) s += __shfl_xor_sync(0xffffffffu, s, o);
    if (lane == 0) rbuf[wid] = s;
    __syncthreads();
    if (tid == 0) {
        float t = 0.f;
        #pragma unroll
        for (int i = 0; i < 8; i++) t += rbuf[i];
        stats[0] = t * (1.0f/CC);
    }
    __syncthreads();
    float mu = stats[0];
    float d0 = v0 - mu, d1 = v1 - mu;
    float q = d0*d0 + d1*d1;
    #pragma unroll
    for (int o = 16; o > 0; o >>= 1) q += __shfl_xor_sync(0xffffffffu, q, o);
    if (lane == 0) rbuf[wid] = q;
    __syncthreads();
    if (tid == 0) {
        float t = 0.f;
        #pragma unroll
        for (int i = 0; i < 8; i++) t += rbuf[i];
        stats[1] = rsqrtf(t * (1.0f/CC) + 1e-5f);
    }
    __syncthreads();
    float rstd = stats[1];
    out[row*CC + tid]       = d0 * rstd * w[tid]       + b[tid];
    out[row*CC + tid + 256] = d1 * rstd * w[tid + 256] + b[tid + 256];
}

// ---------------- tf32 tensor-core NT GEMM, cp.async 3-stage, no cvt ---------
// EPI: 0=bias, 1=bias+res, 2=bias+GELU, 3=raw partial (split-K, no bias)
__device__ __forceinline__ void mma_tf32(float c[4], const uint32_t a[4], const uint32_t b[2]) {
    asm volatile(
        "mma.sync.aligned.m16n8k8.row.col.f32.tf32.tf32.f32 "
        "{%0,%1,%2,%3}, {%4,%5,%6,%7}, {%8,%9}, {%0,%1,%2,%3};\n"
        : "+f"(c[0]), "+f"(c[1]), "+f"(c[2]), "+f"(c[3])
        : "r"(a[0]), "r"(a[1]), "r"(a[2]), "r"(a[3]), "r"(b[0]), "r"(b[1]));
}
__device__ __forceinline__ float epi_apply(float v, float r, int EPI) {
    if (EPI == 1) v += r;
    if (EPI == 2) v = 0.5f * v * (1.0f + erff(v * 0.70710678118654752f));
    return v;
}

// BM=64, BN=64, BK=32, 128 threads (4 warps, 2x2), 3-stage cp.async
// Ksub: K-range handled by this z-slice (Ksub == Kfull when no split).
template<int BM, int EPI, bool WKT>
__global__ void __launch_bounds__(128)
gemm_pl(const float* __restrict__ A, const float* __restrict__ B,
        const float* __restrict__ bias, const float* __restrict__ res,
        float* __restrict__ Cout, float* __restrict__ Kt,
        int M, int N, int Kfull, int Ksub) {
    constexpr int BN = 64, PAD = 36;
    constexpr int MI = BM / 32;
    constexpr int NI = 4;
    constexpr int CA = BM * 8 / 128;
    constexpr int CB = BN * 8 / 128;

    extern __shared__ float sm[];
    float* As = sm;
    float* Bs = sm + 3*BM*PAD;

    int tid = threadIdx.x;
    int warp = tid >> 5, lane = tid & 31;
    int wm = warp & 1, wn = warp >> 1;
    int qr = lane >> 2, qc = lane & 3;
    int bm = blockIdx.y * BM, bn = blockIdx.x * BN;
    int kz = blockIdx.z;
    A += (size_t)kz * Ksub;
    B += (size_t)kz * Ksub;
    const int KT = Ksub >> 5;

    float acc[MI][NI][4] = {};

    auto loadtile = [&](int st, int k0) {
        #pragma unroll
        for (int c = 0; c < CA; c++) {
            int ch = tid + c*128;
            int r = ch >> 3, c4 = (ch & 7) << 2;
            cp16(&As[(st*BM + r)*PAD + c4], A + (size_t)(bm + r)*Kfull + k0 + c4);
        }
        #pragma unroll
        for (int c = 0; c < CB; c++) {
            int ch = tid + c*128;
            int r = ch >> 3, c4 = (ch & 7) << 2;
            cp16(&Bs[(st*BN + r)*PAD + c4], B + (size_t)(bn + r)*Kfull + k0 + c4);
        }
    };

    loadtile(0, 0);  cp_commit();
    loadtile(1, 32); cp_commit();

    for (int kt = 0; kt < KT; kt++) {
        cp_wait<1>();
        __syncthreads();
        if (kt + 2 < KT) loadtile((kt + 2) % 3, (kt + 2) << 5);
        cp_commit();
        int st = kt % 3;
        const float* as = As + st*BM*PAD;
        const float* bs = Bs + st*BN*PAD;
        #pragma unroll
        for (int ko = 0; ko < 32; ko += 8) {
            uint32_t af[MI][4], bf[NI][2];
            #pragma unroll
            for (int mi = 0; mi < MI; mi++) {
                int row = wm*(MI*16) + mi*16 + qr;
                af[mi][0] = __float_as_uint(as[(row    )*PAD + ko + qc]);
                af[mi][1] = __float_as_uint(as[(row + 8)*PAD + ko + qc]);
                af[mi][2] = __float_as_uint(as[(row    )*PAD + ko + 4 + qc]);
                af[mi][3] = __float_as_uint(as[(row + 8)*PAD + ko + 4 + qc]);
            }
            #pragma unroll
            for (int ni = 0; ni < NI; ni++) {
                int col = wn*32 + ni*8 + qr;
                bf[ni][0] = __float_as_uint(bs[col*PAD + ko + qc]);
                bf[ni][1] = __float_as_uint(bs[col*PAD + ko + 4 + qc]);
            }
            #pragma unroll
            for (int mi = 0; mi < MI; mi++)
                #pragma unroll
                for (int ni = 0; ni < NI; ni++)
                    mma_tf32(acc[mi][ni], af[mi], bf[ni]);
        }
        __syncthreads();
    }

    // epilogue
    #pragma unroll
    for (int mi = 0; mi < MI; mi++) {
        int row0 = bm + wm*(MI*16) + mi*16 + qr;
        #pragma unroll
        for (int ni = 0; ni < NI; ni++) {
            int col = bn + wn*32 + ni*8 + qc*2;
            if (EPI == 3) {
                float* cp0 = Cout + ((size_t)kz*M + row0)*N + col;
                float* cp1 = Cout + ((size_t)kz*M + row0 + 8)*N + col;
                *(float2*)cp0 = make_float2(acc[mi][ni][0], acc[mi][ni][1]);
                *(float2*)cp1 = make_float2(acc[mi][ni][2], acc[mi][ni][3]);
                continue;
            }
            float b0 = bias[col], b1 = bias[col + 1];
            float* cp0 = Cout + (size_t)row0*N + col;
            float* cp1 = Cout + (size_t)(row0 + 8)*N + col;
            float r00 = 0.f, r01 = 0.f, r10 = 0.f, r11 = 0.f;
            if (EPI == 1) {
                const float* rp0 = res + (size_t)row0*N + col;
                const float* rp1 = res + (size_t)(row0 + 8)*N + col;
                r00 = rp0[0]; r01 = rp0[1]; r10 = rp1[0]; r11 = rp1[1];
            }
            float2 o0, o1;
            o0.x = epi_apply(acc[mi][ni][0] + b0, r00, EPI);
            o0.y = epi_apply(acc[mi][ni][1] + b1, r01, EPI);
            o1.x = epi_apply(acc[mi][ni][2] + b0, r10, EPI);
            o1.y = epi_apply(acc[mi][ni][3] + b1, r11, EPI);
            *(float2*)cp0 = o0;
            *(float2*)cp1 = o1;
            if (WKT && col >= CC && col < 2*CC) {   // fused K transpose
                int kc = col - CC;
                Kt[(size_t)kc*TT + row0]           = o0.x;
                Kt[(size_t)(kc + 1)*TT + row0]     = o0.y;
                Kt[(size_t)kc*TT + row0 + 8]       = o1.x;
                Kt[(size_t)(kc + 1)*TT + row0 + 8] = o1.y;
            }
        }
    }
}

// ---------------- split-K reduce: out = sum4(part) + bias + res --------------
__global__ void reduce4(const float* __restrict__ part, const float* __restrict__ bias,
                        const float* __restrict__ res, float* __restrict__ out) {
    int idx = blockIdx.x*256 + threadIdx.x;     // 49152 float4s
    const int MN4 = TT*CC/4;
    const float4* p = (const float4*)part;
    float4 a = p[idx], b = p[idx + MN4], c = p[idx + 2*MN4], d = p[idx + 3*MN4];
    float4 bb = ((const float4*)bias)[idx & (CC/4 - 1)];
    float4 rr = ((const float4*)res)[idx];
    float4 o;
    o.x = a.x + b.x + c.x + d.x + bb.x + rr.x;
    o.y = a.y + b.y + c.y + d.y + bb.y + rr.y;
    o.z = a.z + b.z + c.z + d.z + bb.z + rr.z;
    o.w = a.w + b.w + c.w + d.w + bb.w + rr.w;
    ((float4*)out)[idx] = o;
}

// ---------------- gather attention: block per (i,h), 128 thr, vectorized -----
__global__ void attn2(const float* __restrict__ qkv, const float* __restrict__ Kt,
                      const int* __restrict__ bm,
                      const float* __restrict__ EKt, const float* __restrict__ EV,
                      const float* __restrict__ abe, float* __restrict__ y) {
    int i = TT - 1 - blockIdx.x;          // heavy blocks first
    int h = blockIdx.y;
    int tid = threadIdx.x;                // 128
    int lane = tid & 31, wid = tid >> 5;

    __shared__ float  qe_s[DD*EE];        // [d][e] = q[d]*EK[e][d]
    __shared__ float4 EV_s[EE*16];        // [e][d4]
    __shared__ float  ab_s[EE];
    __shared__ float  s_s[TT];
    __shared__ int    e_s[TT];
    __shared__ float4 psum[8][16];
    __shared__ float  rbuf[4];
    __shared__ float  resv[2];

    const float* EKh = EKt + h*DD*EE;
    #pragma unroll
    for (int k = 0; k < 8; k++) {         // 1024 / 128
        int idx = tid + k*128;
        int d = idx >> 4;
        qe_s[idx] = qkv[(size_t)i*3*CC + h*DD + d] * EKh[idx];
    }
    #pragma unroll
    for (int k = 0; k < 2; k++) {         // 256 float4 / 128
        int idx = tid + k*128;            // e*16 + d4
        EV_s[idx] = ((const float4*)EV)[(size_t)(idx >> 4)*(CC/4) + h*16 + (idx & 15)];
    }
    if (tid < EE) ab_s[tid] = abe[tid*HH + h];
    __syncthreads();

    // pass 1: 4 j's per thread via float4 rows of Kt (over-compute past i is
    // harmless: bias_matrix values are always valid indices in [0,16))
    const float4* Kt4 = (const float4*)(Kt + (size_t)h*DD*TT);
    const int4*   bm4 = (const int4*)(bm + (size_t)i*TT);
    for (int g = tid; 4*g <= i; g += 128) {
        int4 e4 = bm4[g];
        float4 s = make_float4(0.f, 0.f, 0.f, 0.f);
        #pragma unroll 8
        for (int d = 0; d < DD; d++) {
            float4 k4 = Kt4[d*(TT/4) + g];
            const float* qe = qe_s + d*EE;
            s.x = fmaf(qe[e4.x], k4.x, s.x);
            s.y = fmaf(qe[e4.y], k4.y, s.y);
            s.z = fmaf(qe[e4.z], k4.z, s.z);
            s.w = fmaf(qe[e4.w], k4.w, s.w);
        }
        float4 o;
        o.x = s.x * 0.125f + ab_s[e4.x];
        o.y = s.y * 0.125f + ab_s[e4.y];
        o.z = s.z * 0.125f + ab_s[e4.z];
        o.w = s.w * 0.125f + ab_s[e4.w];
        ((float4*)s_s)[g] = o;
        ((int4*)e_s)[g] = e4;
    }
    __syncthreads();

    // block max over valid j
    float lm = -1e30f;
    for (int j = tid; j <= i; j += 128) lm = fmaxf(lm, s_s[j]);
    #pragma unroll
    for (int o = 16; o > 0; o >>= 1) lm = fmaxf(lm, __shfl_xor_sync(0xffffffffu, lm, o));
    if (lane == 0) rbuf[wid] = lm;
    __syncthreads();
    if (tid == 0) resv[0] = fmaxf(fmaxf(rbuf[0], rbuf[1]), fmaxf(rbuf[2], rbuf[3]));
    __syncthreads();
    float m = resv[0];

    // exp + sum
    float ls = 0.f;
    for (int j = tid; j <= i; j += 128) {
        float p = __expf(s_s[j] - m);
        s_s[j] = p;
        ls += p;
    }
    #pragma unroll
    for (int o = 16; o > 0; o >>= 1) ls += __shfl_xor_sync(0xffffffffu, ls, o);
    if (lane == 0) rbuf[wid] = ls;
    __syncthreads();
    if (tid == 0) resv[1] = 1.0f / (rbuf[0] + rbuf[1] + rbuf[2] + rbuf[3]);
    __syncthreads();
    float inv = resv[1];

    // pass 2: 8 j-slices x 16 d4-threads, float4 V and EV
    int slice = tid >> 4, d4 = tid & 15;
    const float4* qkv4 = (const float4*)qkv;
    float4 acc = make_float4(0.f, 0.f, 0.f, 0.f);
    for (int j = slice; j <= i; j += 8) {
        float p = s_s[j];
        int e = e_s[j];
        float4 vv = qkv4[((size_t)j*3*CC + 2*CC)/4 + h*16 + d4];
        float4 ev = EV_s[e*16 + d4];
        acc.x = fmaf(p, vv.x * ev.x, acc.x);
        acc.y = fmaf(p, vv.y * ev.y, acc.y);
        acc.z = fmaf(p, vv.z * ev.z, acc.z);
        acc.w = fmaf(p, vv.w * ev.w, acc.w);
    }
    psum[slice][d4] = acc;
    __syncthreads();
    if (tid < 16) {
        float4 a = psum[0][tid];
        #pragma unroll
        for (int s2 = 1; s2 < 8; s2++) {
            float4 b = psum[s2][tid];
            a.x += b.x; a.y += b.y; a.z += b.z; a.w += b.w;
        }
        float4 o = make_float4(a.x*inv, a.y*inv, a.z*inv, a.w*inv);
        ((float4*)(y + (size_t)i*CC + h*DD))[tid] = o;
    }
}

// ---------------- host launch ------------------------------------------------
extern "C" void kernel_launch(void* const* d_in, const int* in_sizes, int n_in,
                              void* d_out, int out_size) {
    const float* x        = (const float*)d_in[0];
    const int*   bmx      = (const int*)  d_in[1];
    const float* ln1_w    = (const float*)d_in[2];
    const float* ln1_b    = (const float*)d_in[3];
    const float* w_attn_w = (const float*)d_in[4];
    const float* w_attn_b = (const float*)d_in[5];
    const float* w_proj_w = (const float*)d_in[6];
    const float* w_proj_b = (const float*)d_in[7];
    const float* abe      = (const float*)d_in[8];
    const float* edge_emb = (const float*)d_in[9];
    const float* wek      = (const float*)d_in[10];
    const float* bek      = (const float*)d_in[11];
    const float* wev      = (const float*)d_in[12];
    const float* bev      = (const float*)d_in[13];
    const float* ln2_w    = (const float*)d_in[14];
    const float* ln2_b    = (const float*)d_in[15];
    const float* c_fc_w   = (const float*)d_in[16];
    const float* c_fc_b   = (const float*)d_in[17];
    const float* c_proj_w = (const float*)d_in[18];
    const float* c_proj_b = (const float*)d_in[19];
    float* out = (float*)d_out;

    float *pH, *pQKV, *pEKt, *pEV, *pKt, *pY, *pX1, *pH2, *pFC, *pPart;
    cudaGetSymbolAddress((void**)&pH,    g_h);
    cudaGetSymbolAddress((void**)&pQKV,  g_qkv);
    cudaGetSymbolAddress((void**)&pEKt,  g_EKt);
    cudaGetSymbolAddress((void**)&pEV,   g_EV);
    cudaGetSymbolAddress((void**)&pKt,   g_Kt);
    cudaGetSymbolAddress((void**)&pY,    g_y);
    cudaGetSymbolAddress((void**)&pX1,   g_x1);
    cudaGetSymbolAddress((void**)&pH2,   g_h2);
    cudaGetSymbolAddress((void**)&pFC,   g_fc);
    cudaGetSymbolAddress((void**)&pPart, g_part);

    constexpr int SM64 = 3*(64 + 64)*36*4;   // 55296 B
    cudaFuncSetAttribute(gemm_pl<64,0,true >, cudaFuncAttributeMaxDynamicSharedMemorySize, SM64);
    cudaFuncSetAttribute(gemm_pl<64,2,false>, cudaFuncAttributeMaxDynamicSharedMemorySize, SM64);
    cudaFuncSetAttribute(gemm_pl<64,3,false>, cudaFuncAttributeMaxDynamicSharedMemorySize, SM64);

    // 1. edge tables
    edge_pre<<<EE, CC>>>(edge_emb, wek, bek, wev, bev, pEKt, pEV);
    // 2. LN1
    ln_kernel<<<TT, 256>>>(x, ln1_w, ln1_b, pH);
    // 3. QKV = LN1 @ w_attn^T + b (384 x 1536 x 512), fused K-transpose
    gemm_pl<64,0,true><<<dim3(3*CC/64, TT/64), 128, SM64>>>(
        pH, w_attn_w, w_attn_b, nullptr, pQKV, pKt, TT, 3*CC, CC, CC);
    // 4. gather attention
    attn2<<<dim3(TT, HH), 128>>>(pQKV, pKt, bmx, pEKt, pEV, abe, pY);
    // 5. x1 = x + y @ w_proj^T + b (split-K=4: 8x6x4 = 192 blocks)
    gemm_pl<64,3,false><<<dim3(CC/64, TT/64, 4), 128, SM64>>>(
        pY, w_proj_w, nullptr, nullptr, pPart, nullptr, TT, CC, CC, CC/4);
    reduce4<<<TT*CC/1024, 256>>>(pPart, w_proj_b, x, pX1);
    // 6. LN2
    ln_kernel<<<TT, 256>>>(pX1, ln2_w, ln2_b, pH2);
    // 7. fc = gelu(h2 @ c_fc^T + b) (384 x 2048 x 512)
    gemm_pl<64,2,false><<<dim3(4*CC/64, TT/64), 128, SM64>>>(
        pH2, c_fc_w, c_fc_b, nullptr, pFC, nullptr, TT, 4*CC, CC, CC);
    // 8. out = x1 + fc @ c_proj^T + b (split-K=4: 192 blocks, K=512 each)
    gemm_pl<64,3,false><<<dim3(CC/64, TT/64, 4), 128, SM64>>>(
        pFC, c_proj_w, nullptr, nullptr, pPart, nullptr, TT, CC, 4*CC, CC);
    reduce4<<<TT*CC/1024, 256>>>(pPart, c_proj_b, pX1, out);
}

// round 13
// speedup vs baseline: 1.7492x; 1.0324x over previous
#include <cuda_runtime.h>
#include <math.h>
#include <stdint.h>

#define TT 384
#define CC 512
#define HH 8
#define DD 64
#define EE 16

// ---------------- scratch (device globals; no allocs allowed) ----------------
__device__ float g_h   [TT*CC];       // LN1 output
__device__ float g_qkv [TT*3*CC];     // QKV
__device__ float g_EV  [EE*CC];       // edge-v table [e][c]
__device__ float g_EKt [CC*EE];       // edge-k table transposed [c][e]
__device__ float g_Kt  [CC*TT];       // K transposed: [c][j]
__device__ float g_y   [TT*CC];       // attention output (pre-proj)
__device__ float g_x1  [TT*CC];       // x + attn
__device__ float g_h2  [TT*CC];       // LN2 output
__device__ float g_fc  [TT*4*CC];     // GELU(fc)
__device__ float g_part[4*TT*CC];     // split-K partials

// ---------------- cp.async helpers ------------------------------------------
__device__ __forceinline__ void cp16(void* smem, const void* gmem) {
    uint32_t s = (uint32_t)__cvta_generic_to_shared(smem);
    asm volatile("cp.async.cg.shared.global [%0], [%1], 16;\n" :: "r"(s), "l"(gmem));
}
__device__ __forceinline__ void cp_commit() {
    asm volatile("cp.async.commit_group;\n");
}
template<int N>
__device__ __forceinline__ void cp_wait() {
    asm volatile("cp.async.wait_group %0;\n" :: "n"(N));
}

// ---------------- edge table precompute: EKt/EV = edge_emb @ W^T + b ---------
__global__ void edge_pre(const float* __restrict__ emb,
                         const float* __restrict__ Wk, const float* __restrict__ bk,
                         const float* __restrict__ Wv, const float* __restrict__ bv,
                         float* __restrict__ EKt, float* __restrict__ EV) {
    int e = blockIdx.x;           // 16 blocks
    int n = threadIdx.x;          // 512 threads
    __shared__ float er[CC];
    er[n] = emb[e*CC + n];
    __syncthreads();
    const float4* wk = (const float4*)(Wk + n*CC);
    const float4* wv = (const float4*)(Wv + n*CC);
    float sk = 0.f, sv = 0.f;
    #pragma unroll 4
    for (int k = 0; k < CC/4; k++) {
        float4 a = wk[k], b = wv[k];
        float e0 = er[4*k+0], e1 = er[4*k+1], e2 = er[4*k+2], e3 = er[4*k+3];
        sk = fmaf(e0,a.x, fmaf(e1,a.y, fmaf(e2,a.z, fmaf(e3,a.w, sk))));
        sv = fmaf(e0,b.x, fmaf(e1,b.y, fmaf(e2,b.z, fmaf(e3,b.w, sv))));
    }
    EKt[n*EE + e] = sk + bk[n];
    EV [e*CC + n] = sv + bv[n];
}

// ---------------- layernorm (row of 512, 256 threads/row) -------------------
__global__ void ln_kernel(const float* __restrict__ x, const float* __restrict__ w,
                          const float* __restrict__ b, float* __restrict__ out) {
    int row = blockIdx.x;
    int tid = threadIdx.x;                 // 256
    int lane = tid & 31, wid = tid >> 5;
    const float* xr = x + row*CC;
    float v0 = xr[tid], v1 = xr[tid + 256];

    __shared__ float rbuf[8];
    __shared__ float stats[2];

    float s = v0 + v1;
    #pragma unroll
    for (int o = 16; o > 0; o >>= 1) s += __shfl_xor_sync(0xffffffffu, s, o);
    if (lane == 0) rbuf[wid] = s;
    __syncthreads();
    if (tid == 0) {
        float t = 0.f;
        #pragma unroll
        for (int i = 0; i < 8; i++) t += rbuf[i];
        stats[0] = t * (1.0f/CC);
    }
    __syncthreads();
    float mu = stats[0];
    float d0 = v0 - mu, d1 = v1 - mu;
    float q = d0*d0 + d1*d1;
    #pragma unroll
    for (int o = 16; o > 0; o >>= 1) q += __shfl_xor_sync(0xffffffffu, q, o);
    if (lane == 0) rbuf[wid] = q;
    __syncthreads();
    if (tid == 0) {
        float t = 0.f;
        #pragma unroll
        for (int i = 0; i < 8; i++) t += rbuf[i];
        stats[1] = rsqrtf(t * (1.0f/CC) + 1e-5f);
    }
    __syncthreads();
    float rstd = stats[1];
    out[row*CC + tid]       = d0 * rstd * w[tid]       + b[tid];
    out[row*CC + tid + 256] = d1 * rstd * w[tid + 256] + b[tid + 256];
}

// ---------------- tf32 tensor-core NT GEMM, cp.async 3-stage, no cvt ---------
// EPI: 0=bias, 1=bias+res, 2=bias+GELU, 3=raw partial (split-K, no bias)
__device__ __forceinline__ void mma_tf32(float c[4], const uint32_t a[4], const uint32_t b[2]) {
    asm volatile(
        "mma.sync.aligned.m16n8k8.row.col.f32.tf32.tf32.f32 "
        "{%0,%1,%2,%3}, {%4,%5,%6,%7}, {%8,%9}, {%0,%1,%2,%3};\n"
        : "+f"(c[0]), "+f"(c[1]), "+f"(c[2]), "+f"(c[3])
        : "r"(a[0]), "r"(a[1]), "r"(a[2]), "r"(a[3]), "r"(b[0]), "r"(b[1]));
}
__device__ __forceinline__ float epi_apply(float v, float r, int EPI) {
    if (EPI == 1) v += r;
    if (EPI == 2) v = 0.5f * v * (1.0f + erff(v * 0.70710678118654752f));
    return v;
}

// BM=64, BN=64, BK=32, 128 threads (4 warps, 2x2), 3-stage cp.async
template<int BM, int EPI, bool WKT>
__global__ void __launch_bounds__(128)
gemm_pl(const float* __restrict__ A, const float* __restrict__ B,
        const float* __restrict__ bias, const float* __restrict__ res,
        float* __restrict__ Cout, float* __restrict__ Kt,
        int M, int N, int Kfull, int Ksub) {
    constexpr int BN = 64, PAD = 36;
    constexpr int MI = BM / 32;
    constexpr int NI = 4;
    constexpr int CA = BM * 8 / 128;
    constexpr int CB = BN * 8 / 128;

    extern __shared__ float sm[];
    float* As = sm;
    float* Bs = sm + 3*BM*PAD;

    int tid = threadIdx.x;
    int warp = tid >> 5, lane = tid & 31;
    int wm = warp & 1, wn = warp >> 1;
    int qr = lane >> 2, qc = lane & 3;
    int bm = blockIdx.y * BM, bn = blockIdx.x * BN;
    int kz = blockIdx.z;
    A += (size_t)kz * Ksub;
    B += (size_t)kz * Ksub;
    const int KT = Ksub >> 5;

    float acc[MI][NI][4] = {};

    auto loadtile = [&](int st, int k0) {
        #pragma unroll
        for (int c = 0; c < CA; c++) {
            int ch = tid + c*128;
            int r = ch >> 3, c4 = (ch & 7) << 2;
            cp16(&As[(st*BM + r)*PAD + c4], A + (size_t)(bm + r)*Kfull + k0 + c4);
        }
        #pragma unroll
        for (int c = 0; c < CB; c++) {
            int ch = tid + c*128;
            int r = ch >> 3, c4 = (ch & 7) << 2;
            cp16(&Bs[(st*BN + r)*PAD + c4], B + (size_t)(bn + r)*Kfull + k0 + c4);
        }
    };

    loadtile(0, 0);  cp_commit();
    loadtile(1, 32); cp_commit();

    for (int kt = 0; kt < KT; kt++) {
        cp_wait<1>();
        __syncthreads();
        if (kt + 2 < KT) loadtile((kt + 2) % 3, (kt + 2) << 5);
        cp_commit();
        int st = kt % 3;
        const float* as = As + st*BM*PAD;
        const float* bs = Bs + st*BN*PAD;
        #pragma unroll
        for (int ko = 0; ko < 32; ko += 8) {
            uint32_t af[MI][4], bf[NI][2];
            #pragma unroll
            for (int mi = 0; mi < MI; mi++) {
                int row = wm*(MI*16) + mi*16 + qr;
                af[mi][0] = __float_as_uint(as[(row    )*PAD + ko + qc]);
                af[mi][1] = __float_as_uint(as[(row + 8)*PAD + ko + qc]);
                af[mi][2] = __float_as_uint(as[(row    )*PAD + ko + 4 + qc]);
                af[mi][3] = __float_as_uint(as[(row + 8)*PAD + ko + 4 + qc]);
            }
            #pragma unroll
            for (int ni = 0; ni < NI; ni++) {
                int col = wn*32 + ni*8 + qr;
                bf[ni][0] = __float_as_uint(bs[col*PAD + ko + qc]);
                bf[ni][1] = __float_as_uint(bs[col*PAD + ko + 4 + qc]);
            }
            #pragma unroll
            for (int mi = 0; mi < MI; mi++)
                #pragma unroll
                for (int ni = 0; ni < NI; ni++)
                    mma_tf32(acc[mi][ni], af[mi], bf[ni]);
        }
        __syncthreads();
    }

    // epilogue
    #pragma unroll
    for (int mi = 0; mi < MI; mi++) {
        int row0 = bm + wm*(MI*16) + mi*16 + qr;
        #pragma unroll
        for (int ni = 0; ni < NI; ni++) {
            int col = bn + wn*32 + ni*8 + qc*2;
            if (EPI == 3) {
                float* cp0 = Cout + ((size_t)kz*M + row0)*N + col;
                float* cp1 = Cout + ((size_t)kz*M + row0 + 8)*N + col;
                *(float2*)cp0 = make_float2(acc[mi][ni][0], acc[mi][ni][1]);
                *(float2*)cp1 = make_float2(acc[mi][ni][2], acc[mi][ni][3]);
                continue;
            }
            float b0 = bias[col], b1 = bias[col + 1];
            float* cp0 = Cout + (size_t)row0*N + col;
            float* cp1 = Cout + (size_t)(row0 + 8)*N + col;
            float r00 = 0.f, r01 = 0.f, r10 = 0.f, r11 = 0.f;
            if (EPI == 1) {
                const float* rp0 = res + (size_t)row0*N + col;
                const float* rp1 = res + (size_t)(row0 + 8)*N + col;
                r00 = rp0[0]; r01 = rp0[1]; r10 = rp1[0]; r11 = rp1[1];
            }
            float2 o0, o1;
            o0.x = epi_apply(acc[mi][ni][0] + b0, r00, EPI);
            o0.y = epi_apply(acc[mi][ni][1] + b1, r01, EPI);
            o1.x = epi_apply(acc[mi][ni][2] + b0, r10, EPI);
            o1.y = epi_apply(acc[mi][ni][3] + b1, r11, EPI);
            *(float2*)cp0 = o0;
            *(float2*)cp1 = o1;
            if (WKT && col >= CC && col < 2*CC) {   // fused K transpose
                int kc = col - CC;
                Kt[(size_t)kc*TT + row0]           = o0.x;
                Kt[(size_t)(kc + 1)*TT + row0]     = o0.y;
                Kt[(size_t)kc*TT + row0 + 8]       = o1.x;
                Kt[(size_t)(kc + 1)*TT + row0 + 8] = o1.y;
            }
        }
    }
}

// ---------------- split-K reduce: out = sum4(part) + bias + res --------------
__global__ void reduce4(const float* __restrict__ part, const float* __restrict__ bias,
                        const float* __restrict__ res, float* __restrict__ out) {
    int idx = blockIdx.x*256 + threadIdx.x;     // 49152 float4s
    const int MN4 = TT*CC/4;
    const float4* p = (const float4*)part;
    float4 a = p[idx], b = p[idx + MN4], c = p[idx + 2*MN4], d = p[idx + 3*MN4];
    float4 bb = ((const float4*)bias)[idx & (CC/4 - 1)];
    float4 rr = ((const float4*)res)[idx];
    float4 o;
    o.x = a.x + b.x + c.x + d.x + bb.x + rr.x;
    o.y = a.y + b.y + c.y + d.y + bb.y + rr.y;
    o.z = a.z + b.z + c.z + d.z + bb.z + rr.z;
    o.w = a.w + b.w + c.w + d.w + bb.w + rr.w;
    ((float4*)out)[idx] = o;
}

// ---------------- gather attention (R9 structure + multi-accumulator) --------
__global__ void attn2(const float* __restrict__ qkv, const float* __restrict__ Kt,
                      const int* __restrict__ bm,
                      const float* __restrict__ EKt, const float* __restrict__ EV,
                      const float* __restrict__ abe, float* __restrict__ y) {
    int i = TT - 1 - blockIdx.x;          // heavy blocks first
    int h = blockIdx.y;
    int tid = threadIdx.x;                // 128
    int lane = tid & 31, wid = tid >> 5;

    __shared__ float qe_s[DD*EE];         // [d][e] = q[d]*EK[e][d]
    __shared__ float EV_s[EE*DD];         // [e][d]
    __shared__ float ab_s[EE];
    __shared__ float s_s[TT];
    __shared__ int   e_s[TT];
    __shared__ float psum[2][DD];
    __shared__ float rbuf[4];
    __shared__ float resv[2];

    const float* EKh = EKt + h*DD*EE;
    #pragma unroll
    for (int k = 0; k < 8; k++) {         // 1024 / 128
        int idx = tid + k*128;
        int d = idx >> 4;
        qe_s[idx] = qkv[(size_t)i*3*CC + h*DD + d] * EKh[idx];
        EV_s[idx] = EV[(size_t)(idx >> 6)*CC + h*DD + (idx & 63)];
    }
    if (tid < EE) ab_s[tid] = abe[tid*HH + h];
    __syncthreads();

    // pass 1: thread-per-j, 4 independent accumulator chains
    const float* KtH = Kt + (size_t)h*DD*TT;
    for (int j = tid; j <= i; j += 128) {
        int e = bm[i*TT + j];
        const float* kp = KtH + j;
        float s0 = 0.f, s1 = 0.f, s2 = 0.f, s3 = 0.f;
        #pragma unroll 4
        for (int d = 0; d < DD; d += 4) {
            s0 = fmaf(qe_s[(d+0)*EE + e], kp[(size_t)(d+0)*TT], s0);
            s1 = fmaf(qe_s[(d+1)*EE + e], kp[(size_t)(d+1)*TT], s1);
            s2 = fmaf(qe_s[(d+2)*EE + e], kp[(size_t)(d+2)*TT], s2);
            s3 = fmaf(qe_s[(d+3)*EE + e], kp[(size_t)(d+3)*TT], s3);
        }
        s_s[j] = ((s0 + s1) + (s2 + s3)) * 0.125f + ab_s[e];
        e_s[j] = e;
    }
    __syncthreads();

    // block max
    float lm = -1e30f;
    for (int j = tid; j <= i; j += 128) lm = fmaxf(lm, s_s[j]);
    #pragma unroll
    for (int o = 16; o > 0; o >>= 1) lm = fmaxf(lm, __shfl_xor_sync(0xffffffffu, lm, o));
    if (lane == 0) rbuf[wid] = lm;
    __syncthreads();
    if (tid == 0) resv[0] = fmaxf(fmaxf(rbuf[0], rbuf[1]), fmaxf(rbuf[2], rbuf[3]));
    __syncthreads();
    float m = resv[0];

    // exp + sum
    float ls = 0.f;
    for (int j = tid; j <= i; j += 128) {
        float p = __expf(s_s[j] - m);
        s_s[j] = p;
        ls += p;
    }
    #pragma unroll
    for (int o = 16; o > 0; o >>= 1) ls += __shfl_xor_sync(0xffffffffu, ls, o);
    if (lane == 0) rbuf[wid] = ls;
    __syncthreads();
    if (tid == 0) resv[1] = 1.0f / (rbuf[0] + rbuf[1] + rbuf[2] + rbuf[3]);
    __syncthreads();
    float inv = resv[1];

    // pass 2: weighted V accumulate, 2 independent chains
    int d = tid & 63, half = tid >> 6;
    float a0 = 0.f, a1 = 0.f;
    int j = half;
    for (; j + 2 <= i; j += 4) {
        int e0 = e_s[j], e1 = e_s[j + 2];
        a0 = fmaf(s_s[j],     qkv[(size_t)j*3*CC + 2*CC + h*DD + d]       * EV_s[e0*DD + d], a0);
        a1 = fmaf(s_s[j + 2], qkv[(size_t)(j + 2)*3*CC + 2*CC + h*DD + d] * EV_s[e1*DD + d], a1);
    }
    for (; j <= i; j += 2) {
        int e = e_s[j];
        a0 = fmaf(s_s[j], qkv[(size_t)j*3*CC + 2*CC + h*DD + d] * EV_s[e*DD + d], a0);
    }
    psum[half][d] = a0 + a1;
    __syncthreads();
    if (tid < DD) y[(size_t)i*CC + h*DD + tid] = (psum[0][tid] + psum[1][tid]) * inv;
}

// ---------------- host launch ------------------------------------------------
extern "C" void kernel_launch(void* const* d_in, const int* in_sizes, int n_in,
                              void* d_out, int out_size) {
    const float* x        = (const float*)d_in[0];
    const int*   bmx      = (const int*)  d_in[1];
    const float* ln1_w    = (const float*)d_in[2];
    const float* ln1_b    = (const float*)d_in[3];
    const float* w_attn_w = (const float*)d_in[4];
    const float* w_attn_b = (const float*)d_in[5];
    const float* w_proj_w = (const float*)d_in[6];
    const float* w_proj_b = (const float*)d_in[7];
    const float* abe      = (const float*)d_in[8];
    const float* edge_emb = (const float*)d_in[9];
    const float* wek      = (const float*)d_in[10];
    const float* bek      = (const float*)d_in[11];
    const float* wev      = (const float*)d_in[12];
    const float* bev      = (const float*)d_in[13];
    const float* ln2_w    = (const float*)d_in[14];
    const float* ln2_b    = (const float*)d_in[15];
    const float* c_fc_w   = (const float*)d_in[16];
    const float* c_fc_b   = (const float*)d_in[17];
    const float* c_proj_w = (const float*)d_in[18];
    const float* c_proj_b = (const float*)d_in[19];
    float* out = (float*)d_out;

    float *pH, *pQKV, *pEKt, *pEV, *pKt, *pY, *pX1, *pH2, *pFC, *pPart;
    cudaGetSymbolAddress((void**)&pH,    g_h);
    cudaGetSymbolAddress((void**)&pQKV,  g_qkv);
    cudaGetSymbolAddress((void**)&pEKt,  g_EKt);
    cudaGetSymbolAddress((void**)&pEV,   g_EV);
    cudaGetSymbolAddress((void**)&pKt,   g_Kt);
    cudaGetSymbolAddress((void**)&pY,    g_y);
    cudaGetSymbolAddress((void**)&pX1,   g_x1);
    cudaGetSymbolAddress((void**)&pH2,   g_h2);
    cudaGetSymbolAddress((void**)&pFC,   g_fc);
    cudaGetSymbolAddress((void**)&pPart, g_part);

    constexpr int SM64 = 3*(64 + 64)*36*4;   // 55296 B
    cudaFuncSetAttribute(gemm_pl<64,0,true >, cudaFuncAttributeMaxDynamicSharedMemorySize, SM64);
    cudaFuncSetAttribute(gemm_pl<64,2,false>, cudaFuncAttributeMaxDynamicSharedMemorySize, SM64);
    cudaFuncSetAttribute(gemm_pl<64,3,false>, cudaFuncAttributeMaxDynamicSharedMemorySize, SM64);

    // 1. edge tables
    edge_pre<<<EE, CC>>>(edge_emb, wek, bek, wev, bev, pEKt, pEV);
    // 2. LN1
    ln_kernel<<<TT, 256>>>(x, ln1_w, ln1_b, pH);
    // 3. QKV = LN1 @ w_attn^T + b (384 x 1536 x 512), fused K-transpose
    gemm_pl<64,0,true><<<dim3(3*CC/64, TT/64), 128, SM64>>>(
        pH, w_attn_w, w_attn_b, nullptr, pQKV, pKt, TT, 3*CC, CC, CC);
    // 4. gather attention
    attn2<<<dim3(TT, HH), 128>>>(pQKV, pKt, bmx, pEKt, pEV, abe, pY);
    // 5. x1 = x + y @ w_proj^T + b (split-K=4: 192 blocks)
    gemm_pl<64,3,false><<<dim3(CC/64, TT/64, 4), 128, SM64>>>(
        pY, w_proj_w, nullptr, nullptr, pPart, nullptr, TT, CC, CC, CC/4);
    reduce4<<<TT*CC/1024, 256>>>(pPart, w_proj_b, x, pX1);
    // 6. LN2
    ln_kernel<<<TT, 256>>>(pX1, ln2_w, ln2_b, pH2);
    // 7. fc = gelu(h2 @ c_fc^T + b) (384 x 2048 x 512)
    gemm_pl<64,2,false><<<dim3(4*CC/64, TT/64), 128, SM64>>>(
        pH2, c_fc_w, c_fc_b, nullptr, pFC, nullptr, TT, 4*CC, CC, CC);
    // 8. out = x1 + fc @ c_proj^T + b (split-K=4: 192 blocks, K=512 each)
    gemm_pl<64,3,false><<<dim3(CC/64, TT/64, 4), 128, SM64>>>(
        pFC, c_proj_w, nullptr, nullptr, pPart, nullptr, TT, CC, 4*CC, CC);
    reduce4<<<TT*CC/1024, 256>>>(pPart, c_proj_b, pX1, out);
}

// round 15
// speedup vs baseline: 1.7768x; 1.0157x over previous
#include <cuda_runtime.h>
#include <math.h>
#include <stdint.h>

#define TT 384
#define CC 512
#define HH 8
#define DD 64
#define EE 16

// ---------------- scratch (device globals; no allocs allowed) ----------------
__device__ float g_h   [TT*CC];       // LN1 output
__device__ float g_qkv [TT*3*CC];     // QKV
__device__ float g_EV  [EE*CC];       // edge-v table [e][c]
__device__ float g_EKt [CC*EE];       // edge-k table transposed [c][e]
__device__ float g_Kt  [CC*TT];       // K transposed: [c][j]
__device__ float g_y   [TT*CC];       // attention output (pre-proj)
__device__ float g_x1  [TT*CC];       // x + attn
__device__ float g_h2  [TT*CC];       // LN2 output
__device__ float g_fc  [TT*4*CC];     // GELU(fc)
__device__ float g_part[4*TT*CC];     // split-K partials

// ---------------- cp.async helpers ------------------------------------------
__device__ __forceinline__ void cp16(void* smem, const void* gmem) {
    uint32_t s = (uint32_t)__cvta_generic_to_shared(smem);
    asm volatile("cp.async.cg.shared.global [%0], [%1], 16;\n" :: "r"(s), "l"(gmem));
}
__device__ __forceinline__ void cp_commit() {
    asm volatile("cp.async.commit_group;\n");
}
template<int N>
__device__ __forceinline__ void cp_wait() {
    asm volatile("cp.async.wait_group %0;\n" :: "n"(N));
}

// ---------------- edge table precompute: EKt/EV = edge_emb @ W^T + b ---------
__global__ void edge_pre(const float* __restrict__ emb,
                         const float* __restrict__ Wk, const float* __restrict__ bk,
                         const float* __restrict__ Wv, const float* __restrict__ bv,
                         float* __restrict__ EKt, float* __restrict__ EV) {
    int e = blockIdx.x;           // 16 blocks
    int n = threadIdx.x;          // 512 threads
    __shared__ float er[CC];
    er[n] = emb[e*CC + n];
    __syncthreads();
    const float4* wk = (const float4*)(Wk + n*CC);
    const float4* wv = (const float4*)(Wv + n*CC);
    float sk = 0.f, sv = 0.f;
    #pragma unroll 4
    for (int k = 0; k < CC/4; k++) {
        float4 a = wk[k], b = wv[k];
        float e0 = er[4*k+0], e1 = er[4*k+1], e2 = er[4*k+2], e3 = er[4*k+3];
        sk = fmaf(e0,a.x, fmaf(e1,a.y, fmaf(e2,a.z, fmaf(e3,a.w, sk))));
        sv = fmaf(e0,b.x, fmaf(e1,b.y, fmaf(e2,b.z, fmaf(e3,b.w, sv))));
    }
    EKt[n*EE + e] = sk + bk[n];
    EV [e*CC + n] = sv + bv[n];
}

// ---------------- layernorm (row of 512, 256 threads/row) -------------------
__global__ void ln_kernel(const float* __restrict__ x, const float* __restrict__ w,
                          const float* __restrict__ b, float* __restrict__ out) {
    int row = blockIdx.x;
    int tid = threadIdx.x;                 // 256
    int lane = tid & 31, wid = tid >> 5;
    const float* xr = x + row*CC;
    float v0 = xr[tid], v1 = xr[tid + 256];

    __shared__ float rbuf[8];
    __shared__ float stats[2];

    float s = v0 + v1;
    #pragma unroll
    for (int o = 16; o > 0; o >>= 1) s += __shfl_xor_sync(0xffffffffu, s, o);
    if (lane == 0) rbuf[wid] = s;
    __syncthreads();
    if (tid == 0) {
        float t = 0.f;
        #pragma unroll
        for (int i = 0; i < 8; i++) t += rbuf[i];
        stats[0] = t * (1.0f/CC);
    }
    __syncthreads();
    float mu = stats[0];
    float d0 = v0 - mu, d1 = v1 - mu;
    float q = d0*d0 + d1*d1;
    #pragma unroll
    for (int o = 16; o > 0; o >>= 1) q += __shfl_xor_sync(0xffffffffu, q, o);
    if (lane == 0) rbuf[wid] = q;
    __syncthreads();
    if (tid == 0) {
        float t = 0.f;
        #pragma unroll
        for (int i = 0; i < 8; i++) t += rbuf[i];
        stats[1] = rsqrtf(t * (1.0f/CC) + 1e-5f);
    }
    __syncthreads();
    float rstd = stats[1];
    out[row*CC + tid]       = d0 * rstd * w[tid]       + b[tid];
    out[row*CC + tid + 256] = d1 * rstd * w[tid + 256] + b[tid + 256];
}

// ---------------- tf32 tensor-core NT GEMM, cp.async 3-stage, no cvt ---------
// EPI: 0=bias, 1=bias+res, 2=bias+GELU, 3=raw partial (split-K, no bias)
__device__ __forceinline__ void mma_tf32(float c[4], const uint32_t a[4], const uint32_t b[2]) {
    asm volatile(
        "mma.sync.aligned.m16n8k8.row.col.f32.tf32.tf32.f32 "
        "{%0,%1,%2,%3}, {%4,%5,%6,%7}, {%8,%9}, {%0,%1,%2,%3};\n"
        : "+f"(c[0]), "+f"(c[1]), "+f"(c[2]), "+f"(c[3])
        : "r"(a[0]), "r"(a[1]), "r"(a[2]), "r"(a[3]), "r"(b[0]), "r"(b[1]));
}
__device__ __forceinline__ float epi_apply(float v, float r, int EPI) {
    if (EPI == 1) v += r;
    if (EPI == 2) v = 0.5f * v * (1.0f + erff(v * 0.70710678118654752f));
    return v;
}

// BN=64, BK=32, 3-stage cp.async. BM in {64,128}; NTHR = 2*BM.
// Warp grid: NWM x 2 (NWM = BM/32), warp tile 32x32 (MI=2 x NI=4 m16n8k8).
template<int BM, int NTHR, int EPI, bool WKT>
__global__ void __launch_bounds__(NTHR)
gemm_pl(const float* __restrict__ A, const float* __restrict__ B,
        const float* __restrict__ bias, const float* __restrict__ res,
        float* __restrict__ Cout, float* __restrict__ Kt,
        int M, int N, int Kfull, int Ksub) {
    constexpr int BN = 64, PAD = 36;
    constexpr int NWM = BM / 32;             // warps along m
    constexpr int MI = 2;                    // m16 frags per warp (warp m-width 32)
    constexpr int NI = 4;                    // n8 frags per warp (warp n-width 32)
    constexpr int CA = BM * 8 / NTHR;        // float4 chunks per thread (A)
    constexpr int CB = BN * 8 / NTHR;        // (B)

    extern __shared__ float sm[];
    float* As = sm;
    float* Bs = sm + 3*BM*PAD;

    int tid = threadIdx.x;
    int warp = tid >> 5, lane = tid & 31;
    int wm = warp % NWM, wn = warp / NWM;
    int qr = lane >> 2, qc = lane & 3;
    int bm = blockIdx.y * BM, bn = blockIdx.x * BN;
    int kz = blockIdx.z;
    A += (size_t)kz * Ksub;
    B += (size_t)kz * Ksub;
    const int KT = Ksub >> 5;

    float acc[MI][NI][4] = {};

    auto loadtile = [&](int st, int k0) {
        #pragma unroll
        for (int c = 0; c < CA; c++) {
            int ch = tid + c*NTHR;
            int r = ch >> 3, c4 = (ch & 7) << 2;
            cp16(&As[(st*BM + r)*PAD + c4], A + (size_t)(bm + r)*Kfull + k0 + c4);
        }
        #pragma unroll
        for (int c = 0; c < CB; c++) {
            int ch = tid + c*NTHR;
            int r = ch >> 3, c4 = (ch & 7) << 2;
            cp16(&Bs[(st*BN + r)*PAD + c4], B + (size_t)(bn + r)*Kfull + k0 + c4);
        }
    };

    loadtile(0, 0);  cp_commit();
    loadtile(1, 32); cp_commit();

    for (int kt = 0; kt < KT; kt++) {
        cp_wait<1>();
        __syncthreads();
        if (kt + 2 < KT) loadtile((kt + 2) % 3, (kt + 2) << 5);
        cp_commit();
        int st = kt % 3;
        const float* as = As + st*BM*PAD;
        const float* bs = Bs + st*BN*PAD;
        #pragma unroll
        for (int ko = 0; ko < 32; ko += 8) {
            uint32_t af[MI][4], bf[NI][2];
            #pragma unroll
            for (int mi = 0; mi < MI; mi++) {
                int row = wm*32 + mi*16 + qr;
                af[mi][0] = __float_as_uint(as[(row    )*PAD + ko + qc]);
                af[mi][1] = __float_as_uint(as[(row + 8)*PAD + ko + qc]);
                af[mi][2] = __float_as_uint(as[(row    )*PAD + ko + 4 + qc]);
                af[mi][3] = __float_as_uint(as[(row + 8)*PAD + ko + 4 + qc]);
            }
            #pragma unroll
            for (int ni = 0; ni < NI; ni++) {
                int col = wn*32 + ni*8 + qr;
                bf[ni][0] = __float_as_uint(bs[col*PAD + ko + qc]);
                bf[ni][1] = __float_as_uint(bs[col*PAD + ko + 4 + qc]);
            }
            #pragma unroll
            for (int mi = 0; mi < MI; mi++)
                #pragma unroll
                for (int ni = 0; ni < NI; ni++)
                    mma_tf32(acc[mi][ni], af[mi], bf[ni]);
        }
        __syncthreads();
    }

    // epilogue
    #pragma unroll
    for (int mi = 0; mi < MI; mi++) {
        int row0 = bm + wm*32 + mi*16 + qr;
        #pragma unroll
        for (int ni = 0; ni < NI; ni++) {
            int col = bn + wn*32 + ni*8 + qc*2;
            if (EPI == 3) {
                float* cp0 = Cout + ((size_t)kz*M + row0)*N + col;
                float* cp1 = Cout + ((size_t)kz*M + row0 + 8)*N + col;
                *(float2*)cp0 = make_float2(acc[mi][ni][0], acc[mi][ni][1]);
                *(float2*)cp1 = make_float2(acc[mi][ni][2], acc[mi][ni][3]);
                continue;
            }
            float b0 = bias[col], b1 = bias[col + 1];
            float* cp0 = Cout + (size_t)row0*N + col;
            float* cp1 = Cout + (size_t)(row0 + 8)*N + col;
            float r00 = 0.f, r01 = 0.f, r10 = 0.f, r11 = 0.f;
            if (EPI == 1) {
                const float* rp0 = res + (size_t)row0*N + col;
                const float* rp1 = res + (size_t)(row0 + 8)*N + col;
                r00 = rp0[0]; r01 = rp0[1]; r10 = rp1[0]; r11 = rp1[1];
            }
            float2 o0, o1;
            o0.x = epi_apply(acc[mi][ni][0] + b0, r00, EPI);
            o0.y = epi_apply(acc[mi][ni][1] + b1, r01, EPI);
            o1.x = epi_apply(acc[mi][ni][2] + b0, r10, EPI);
            o1.y = epi_apply(acc[mi][ni][3] + b1, r11, EPI);
            *(float2*)cp0 = o0;
            *(float2*)cp1 = o1;
            if (WKT && col >= CC && col < 2*CC) {   // fused K transpose
                int kc = col - CC;
                Kt[(size_t)kc*TT + row0]           = o0.x;
                Kt[(size_t)(kc + 1)*TT + row0]     = o0.y;
                Kt[(size_t)kc*TT + row0 + 8]       = o1.x;
                Kt[(size_t)(kc + 1)*TT + row0 + 8] = o1.y;
            }
        }
    }
}

// ---------------- split-K reduce: out = sum4(part) + bias + res --------------
__global__ void reduce4(const float* __restrict__ part, const float* __restrict__ bias,
                        const float* __restrict__ res, float* __restrict__ out) {
    int idx = blockIdx.x*256 + threadIdx.x;     // 49152 float4s
    const int MN4 = TT*CC/4;
    const float4* p = (const float4*)part;
    float4 a = p[idx], b = p[idx + MN4], c = p[idx + 2*MN4], d = p[idx + 3*MN4];
    float4 bb = ((const float4*)bias)[idx & (CC/4 - 1)];
    float4 rr = ((const float4*)res)[idx];
    float4 o;
    o.x = a.x + b.x + c.x + d.x + bb.x + rr.x;
    o.y = a.y + b.y + c.y + d.y + bb.y + rr.y;
    o.z = a.z + b.z + c.z + d.z + bb.z + rr.z;
    o.w = a.w + b.w + c.w + d.w + bb.w + rr.w;
    ((float4*)out)[idx] = o;
}

// ---------------- gather attention (lean prologue, multi-accumulator) --------
__global__ void attn2(const float* __restrict__ qkv, const float* __restrict__ Kt,
                      const int* __restrict__ bm,
                      const float* __restrict__ EKt, const float* __restrict__ EV,
                      const float* __restrict__ abe, float* __restrict__ y) {
    int i = TT - 1 - blockIdx.x;          // heavy blocks first
    int h = blockIdx.y;
    int tid = threadIdx.x;                // 128
    int lane = tid & 31, wid = tid >> 5;

    __shared__ float qe_s[DD*EE];         // [d][e] = q[d]*EK[e][d]
    __shared__ float ab_s[EE];
    __shared__ float s_s[TT];
    __shared__ int   e_s[TT];
    __shared__ float psum[2][DD];
    __shared__ float rbuf[4];
    __shared__ float resv[2];

    const float* EKh = EKt + h*DD*EE;
    #pragma unroll
    for (int k = 0; k < 8; k++) {         // 1024 / 128
        int idx = tid + k*128;
        int d = idx >> 4;
        qe_s[idx] = __ldg(&qkv[(size_t)i*3*CC + h*DD + d]) * __ldg(&EKh[idx]);
    }
    if (tid < EE) ab_s[tid] = abe[tid*HH + h];
    __syncthreads();

    // pass 1: thread-per-j, 4 independent accumulator chains
    const float* KtH = Kt + (size_t)h*DD*TT;
    for (int j = tid; j <= i; j += 128) {
        int e = bm[i*TT + j];
        const float* kp = KtH + j;
        float s0 = 0.f, s1 = 0.f, s2 = 0.f, s3 = 0.f;
        #pragma unroll 4
        for (int d = 0; d < DD; d += 4) {
            s0 = fmaf(qe_s[(d+0)*EE + e], kp[(size_t)(d+0)*TT], s0);
            s1 = fmaf(qe_s[(d+1)*EE + e], kp[(size_t)(d+1)*TT], s1);
            s2 = fmaf(qe_s[(d+2)*EE + e], kp[(size_t)(d+2)*TT], s2);
            s3 = fmaf(qe_s[(d+3)*EE + e], kp[(size_t)(d+3)*TT], s3);
        }
        s_s[j] = ((s0 + s1) + (s2 + s3)) * 0.125f + ab_s[e];
        e_s[j] = e;
    }
    __syncthreads();

    // block max
    float lm = -1e30f;
    for (int j = tid; j <= i; j += 128) lm = fmaxf(lm, s_s[j]);
    #pragma unroll
    for (int o = 16; o > 0; o >>= 1) lm = fmaxf(lm, __shfl_xor_sync(0xffffffffu, lm, o));
    if (lane == 0) rbuf[wid] = lm;
    __syncthreads();
    if (tid == 0) resv[0] = fmaxf(fmaxf(rbuf[0], rbuf[1]), fmaxf(rbuf[2], rbuf[3]));
    __syncthreads();
    float m = resv[0];

    // exp + sum
    float ls = 0.f;
    for (int j = tid; j <= i; j += 128) {
        float p = __expf(s_s[j] - m);
        s_s[j] = p;
        ls += p;
    }
    #pragma unroll
    for (int o = 16; o > 0; o >>= 1) ls += __shfl_xor_sync(0xffffffffu, ls, o);
    if (lane == 0) rbuf[wid] = ls;
    __syncthreads();
    if (tid == 0) resv[1] = 1.0f / (rbuf[0] + rbuf[1] + rbuf[2] + rbuf[3]);
    __syncthreads();
    float inv = resv[1];

    // pass 2: weighted V accumulate, 2 chains; EV direct via L1 (coalesced in d)
    int d = tid & 63, half = tid >> 6;
    const float* EVh = EV + h*DD + d;
    float a0 = 0.f, a1 = 0.f;
    int j = half;
    for (; j + 2 <= i; j += 4) {
        int e0 = e_s[j], e1 = e_s[j + 2];
        a0 = fmaf(s_s[j],     qkv[(size_t)j*3*CC + 2*CC + h*DD + d]       * __ldg(EVh + e0*CC), a0);
        a1 = fmaf(s_s[j + 2], qkv[(size_t)(j + 2)*3*CC + 2*CC + h*DD + d] * __ldg(EVh + e1*CC), a1);
    }
    for (; j <= i; j += 2) {
        int e = e_s[j];
        a0 = fmaf(s_s[j], qkv[(size_t)j*3*CC + 2*CC + h*DD + d] * __ldg(EVh + e*CC), a0);
    }
    psum[half][d] = a0 + a1;
    __syncthreads();
    if (tid < DD) y[(size_t)i*CC + h*DD + tid] = (psum[0][tid] + psum[1][tid]) * inv;
}

// ---------------- host launch ------------------------------------------------
extern "C" void kernel_launch(void* const* d_in, const int* in_sizes, int n_in,
                              void* d_out, int out_size) {
    const float* x        = (const float*)d_in[0];
    const int*   bmx      = (const int*)  d_in[1];
    const float* ln1_w    = (const float*)d_in[2];
    const float* ln1_b    = (const float*)d_in[3];
    const float* w_attn_w = (const float*)d_in[4];
    const float* w_attn_b = (const float*)d_in[5];
    const float* w_proj_w = (const float*)d_in[6];
    const float* w_proj_b = (const float*)d_in[7];
    const float* abe      = (const float*)d_in[8];
    const float* edge_emb = (const float*)d_in[9];
    const float* wek      = (const float*)d_in[10];
    const float* bek      = (const float*)d_in[11];
    const float* wev      = (const float*)d_in[12];
    const float* bev      = (const float*)d_in[13];
    const float* ln2_w    = (const float*)d_in[14];
    const float* ln2_b    = (const float*)d_in[15];
    const float* c_fc_w   = (const float*)d_in[16];
    const float* c_fc_b   = (const float*)d_in[17];
    const float* c_proj_w = (const float*)d_in[18];
    const float* c_proj_b = (const float*)d_in[19];
    float* out = (float*)d_out;

    float *pH, *pQKV, *pEKt, *pEV, *pKt, *pY, *pX1, *pH2, *pFC, *pPart;
    cudaGetSymbolAddress((void**)&pH,    g_h);
    cudaGetSymbolAddress((void**)&pQKV,  g_qkv);
    cudaGetSymbolAddress((void**)&pEKt,  g_EKt);
    cudaGetSymbolAddress((void**)&pEV,   g_EV);
    cudaGetSymbolAddress((void**)&pKt,   g_Kt);
    cudaGetSymbolAddress((void**)&pY,    g_y);
    cudaGetSymbolAddress((void**)&pX1,   g_x1);
    cudaGetSymbolAddress((void**)&pH2,   g_h2);
    cudaGetSymbolAddress((void**)&pFC,   g_fc);
    cudaGetSymbolAddress((void**)&pPart, g_part);

    constexpr int SM64  = 3*(64  + 64)*36*4;  // 55296 B
    constexpr int SM128 = 3*(128 + 64)*36*4;  // 82944 B
    cudaFuncSetAttribute((const void*)gemm_pl<64,128,0,true >, cudaFuncAttributeMaxDynamicSharedMemorySize, SM64);
    cudaFuncSetAttribute((const void*)gemm_pl<128,256,2,false>, cudaFuncAttributeMaxDynamicSharedMemorySize, SM128);
    cudaFuncSetAttribute((const void*)gemm_pl<64,128,3,false>, cudaFuncAttributeMaxDynamicSharedMemorySize, SM64);

    // 1. edge tables
    edge_pre<<<EE, CC>>>(edge_emb, wek, bek, wev, bev, pEKt, pEV);
    // 2. LN1
    ln_kernel<<<TT, 256>>>(x, ln1_w, ln1_b, pH);
    // 3. QKV = LN1 @ w_attn^T + b (384 x 1536 x 512), fused K-transpose (144 CTAs)
    gemm_pl<64,128,0,true><<<dim3(3*CC/64, TT/64), 128, SM64>>>(
        pH, w_attn_w, w_attn_b, nullptr, pQKV, pKt, TT, 3*CC, CC, CC);
    // 4. gather attention
    attn2<<<dim3(TT, HH), 128>>>(pQKV, pKt, bmx, pEKt, pEV, abe, pY);
    // 5. x1 = x + y @ w_proj^T + b (split-K=4: 192 blocks)
    gemm_pl<64,128,3,false><<<dim3(CC/64, TT/64, 4), 128, SM64>>>(
        pY, w_proj_w, nullptr, nullptr, pPart, nullptr, TT, CC, CC, CC/4);
    reduce4<<<TT*CC/1024, 256>>>(pPart, w_proj_b, x, pX1);
    // 6. LN2
    ln_kernel<<<TT, 256>>>(pX1, ln2_w, ln2_b, pH2);
    // 7. fc = gelu(h2 @ c_fc^T + b) (384 x 2048 x 512) — BM=128: 96 CTAs, one wave
    gemm_pl<128,256,2,false><<<dim3(4*CC/64, TT/128), 256, SM128>>>(
        pH2, c_fc_w, c_fc_b, nullptr, pFC, nullptr, TT, 4*CC, CC, CC);
    // 8. out = x1 + fc @ c_proj^T + b (split-K=4: 192 blocks, K=512 each)
    gemm_pl<64,128,3,false><<<dim3(CC/64, TT/64, 4), 128, SM64>>>(
        pFC, c_proj_w, nullptr, nullptr, pPart, nullptr, TT, CC, 4*CC, CC);
    reduce4<<<TT*CC/1024, 256>>>(pPart, c_proj_b, pX1, out);
}

// round 17
// speedup vs baseline: 1.8316x; 1.0308x over previous
#include <cuda_runtime.h>
#include <math.h>
#include <stdint.h>

#define TT 384
#define CC 512
#define HH 8
#define DD 64
#define EE 16

// ---------------- scratch (device globals; no allocs allowed) ----------------
__device__ float g_h   [TT*CC];       // LN1 output
__device__ float g_qkv [TT*3*CC];     // QKV
__device__ float g_EV  [EE*CC];       // edge-v table [e][c]
__device__ float g_EKt [CC*EE];       // edge-k table transposed [c][e]
__device__ float g_Kt  [CC*TT];       // K transposed: [c][j]
__device__ float g_y   [TT*CC];       // attention output (pre-proj)
__device__ float g_x1  [TT*CC];       // x + attn
__device__ float g_h2  [TT*CC];       // LN2 output
__device__ float g_fc  [TT*4*CC];     // GELU(fc)
__device__ float g_part[4*TT*CC];     // split-K partials

// ---------------- cp.async helpers ------------------------------------------
__device__ __forceinline__ void cp16(void* smem, const void* gmem) {
    uint32_t s = (uint32_t)__cvta_generic_to_shared(smem);
    asm volatile("cp.async.cg.shared.global [%0], [%1], 16;\n" :: "r"(s), "l"(gmem));
}
__device__ __forceinline__ void cp_commit() {
    asm volatile("cp.async.commit_group;\n");
}
template<int N>
__device__ __forceinline__ void cp_wait() {
    asm volatile("cp.async.wait_group %0;\n" :: "n"(N));
}

// ---------------- edge table precompute: EKt/EV = edge_emb @ W^T + b ---------
__global__ void edge_pre(const float* __restrict__ emb,
                         const float* __restrict__ Wk, const float* __restrict__ bk,
                         const float* __restrict__ Wv, const float* __restrict__ bv,
                         float* __restrict__ EKt, float* __restrict__ EV) {
    int e = blockIdx.x;           // 16 blocks
    int n = threadIdx.x;          // 512 threads
    __shared__ float er[CC];
    er[n] = emb[e*CC + n];
    __syncthreads();
    const float4* wk = (const float4*)(Wk + n*CC);
    const float4* wv = (const float4*)(Wv + n*CC);
    float sk = 0.f, sv = 0.f;
    #pragma unroll 4
    for (int k = 0; k < CC/4; k++) {
        float4 a = wk[k], b = wv[k];
        float e0 = er[4*k+0], e1 = er[4*k+1], e2 = er[4*k+2], e3 = er[4*k+3];
        sk = fmaf(e0,a.x, fmaf(e1,a.y, fmaf(e2,a.z, fmaf(e3,a.w, sk))));
        sv = fmaf(e0,b.x, fmaf(e1,b.y, fmaf(e2,b.z, fmaf(e3,b.w, sv))));
    }
    EKt[n*EE + e] = sk + bk[n];
    EV [e*CC + n] = sv + bv[n];
}

// ---------------- layernorm (row of 512, 256 threads/row) -------------------
__global__ void ln_kernel(const float* __restrict__ x, const float* __restrict__ w,
                          const float* __restrict__ b, float* __restrict__ out) {
    int row = blockIdx.x;
    int tid = threadIdx.x;                 // 256
    int lane = tid & 31, wid = tid >> 5;
    const float* xr = x + row*CC;
    float v0 = xr[tid], v1 = xr[tid + 256];

    __shared__ float rbuf[8];
    __shared__ float stats[2];

    float s = v0 + v1;
    #pragma unroll
    for (int o = 16; o > 0; o >>= 1) s += __shfl_xor_sync(0xffffffffu, s, o);
    if (lane == 0) rbuf[wid] = s;
    __syncthreads();
    if (tid == 0) {
        float t = 0.f;
        #pragma unroll
        for (int i = 0; i < 8; i++) t += rbuf[i];
        stats[0] = t * (1.0f/CC);
    }
    __syncthreads();
    float mu = stats[0];
    float d0 = v0 - mu, d1 = v1 - mu;
    float q = d0*d0 + d1*d1;
    #pragma unroll
    for (int o = 16; o > 0; o >>= 1) q += __shfl_xor_sync(0xffffffffu, q, o);
    if (lane == 0) rbuf[wid] = q;
    __syncthreads();
    if (tid == 0) {
        float t = 0.f;
        #pragma unroll
        for (int i = 0; i < 8; i++) t += rbuf[i];
        stats[1] = rsqrtf(t * (1.0f/CC) + 1e-5f);
    }
    __syncthreads();
    float rstd = stats[1];
    out[row*CC + tid]       = d0 * rstd * w[tid]       + b[tid];
    out[row*CC + tid + 256] = d1 * rstd * w[tid + 256] + b[tid + 256];
}

// ---------------- tf32 tensor-core NT GEMM, cp.async 3-stage, no cvt ---------
// EPI: 0=bias, 1=bias+res, 2=bias+GELU, 3=raw partial (split-K, no bias)
__device__ __forceinline__ void mma_tf32(float c[4], const uint32_t a[4], const uint32_t b[2]) {
    asm volatile(
        "mma.sync.aligned.m16n8k8.row.col.f32.tf32.tf32.f32 "
        "{%0,%1,%2,%3}, {%4,%5,%6,%7}, {%8,%9}, {%0,%1,%2,%3};\n"
        : "+f"(c[0]), "+f"(c[1]), "+f"(c[2]), "+f"(c[3])
        : "r"(a[0]), "r"(a[1]), "r"(a[2]), "r"(a[3]), "r"(b[0]), "r"(b[1]));
}
__device__ __forceinline__ float epi_apply(float v, float r, int EPI) {
    if (EPI == 1) v += r;
    if (EPI == 2) v = 0.5f * v * (1.0f + erff(v * 0.70710678118654752f));
    return v;
}

// BN=64, BK=32, 3-stage cp.async. BM in {64,128}; NTHR = 2*BM.
template<int BM, int NTHR, int EPI, bool WKT>
__global__ void __launch_bounds__(NTHR)
gemm_pl(const float* __restrict__ A, const float* __restrict__ B,
        const float* __restrict__ bias, const float* __restrict__ res,
        float* __restrict__ Cout, float* __restrict__ Kt,
        int M, int N, int Kfull, int Ksub) {
    constexpr int BN = 64, PAD = 36;
    constexpr int NWM = BM / 32;
    constexpr int MI = 2;
    constexpr int NI = 4;
    constexpr int CA = BM * 8 / NTHR;
    constexpr int CB = BN * 8 / NTHR;

    extern __shared__ float sm[];
    float* As = sm;
    float* Bs = sm + 3*BM*PAD;

    int tid = threadIdx.x;
    int warp = tid >> 5, lane = tid & 31;
    int wm = warp % NWM, wn = warp / NWM;
    int qr = lane >> 2, qc = lane & 3;
    int bm = blockIdx.y * BM, bn = blockIdx.x * BN;
    int kz = blockIdx.z;
    A += (size_t)kz * Ksub;
    B += (size_t)kz * Ksub;
    const int KT = Ksub >> 5;

    float acc[MI][NI][4] = {};

    auto loadtile = [&](int st, int k0) {
        #pragma unroll
        for (int c = 0; c < CA; c++) {
            int ch = tid + c*NTHR;
            int r = ch >> 3, c4 = (ch & 7) << 2;
            cp16(&As[(st*BM + r)*PAD + c4], A + (size_t)(bm + r)*Kfull + k0 + c4);
        }
        #pragma unroll
        for (int c = 0; c < CB; c++) {
            int ch = tid + c*NTHR;
            int r = ch >> 3, c4 = (ch & 7) << 2;
            cp16(&Bs[(st*BN + r)*PAD + c4], B + (size_t)(bn + r)*Kfull + k0 + c4);
        }
    };

    loadtile(0, 0);  cp_commit();
    loadtile(1, 32); cp_commit();

    for (int kt = 0; kt < KT; kt++) {
        cp_wait<1>();
        __syncthreads();
        if (kt + 2 < KT) loadtile((kt + 2) % 3, (kt + 2) << 5);
        cp_commit();
        int st = kt % 3;
        const float* as = As + st*BM*PAD;
        const float* bs = Bs + st*BN*PAD;
        #pragma unroll
        for (int ko = 0; ko < 32; ko += 8) {
            uint32_t af[MI][4], bf[NI][2];
            #pragma unroll
            for (int mi = 0; mi < MI; mi++) {
                int row = wm*32 + mi*16 + qr;
                af[mi][0] = __float_as_uint(as[(row    )*PAD + ko + qc]);
                af[mi][1] = __float_as_uint(as[(row + 8)*PAD + ko + qc]);
                af[mi][2] = __float_as_uint(as[(row    )*PAD + ko + 4 + qc]);
                af[mi][3] = __float_as_uint(as[(row + 8)*PAD + ko + 4 + qc]);
            }
            #pragma unroll
            for (int ni = 0; ni < NI; ni++) {
                int col = wn*32 + ni*8 + qr;
                bf[ni][0] = __float_as_uint(bs[col*PAD + ko + qc]);
                bf[ni][1] = __float_as_uint(bs[col*PAD + ko + 4 + qc]);
            }
            #pragma unroll
            for (int mi = 0; mi < MI; mi++)
                #pragma unroll
                for (int ni = 0; ni < NI; ni++)
                    mma_tf32(acc[mi][ni], af[mi], bf[ni]);
        }
        __syncthreads();
    }

    // epilogue
    #pragma unroll
    for (int mi = 0; mi < MI; mi++) {
        int row0 = bm + wm*32 + mi*16 + qr;
        #pragma unroll
        for (int ni = 0; ni < NI; ni++) {
            int col = bn + wn*32 + ni*8 + qc*2;
            if (EPI == 3) {
                float* cp0 = Cout + ((size_t)kz*M + row0)*N + col;
                float* cp1 = Cout + ((size_t)kz*M + row0 + 8)*N + col;
                *(float2*)cp0 = make_float2(acc[mi][ni][0], acc[mi][ni][1]);
                *(float2*)cp1 = make_float2(acc[mi][ni][2], acc[mi][ni][3]);
                continue;
            }
            float b0 = bias[col], b1 = bias[col + 1];
            float* cp0 = Cout + (size_t)row0*N + col;
            float* cp1 = Cout + (size_t)(row0 + 8)*N + col;
            float r00 = 0.f, r01 = 0.f, r10 = 0.f, r11 = 0.f;
            if (EPI == 1) {
                const float* rp0 = res + (size_t)row0*N + col;
                const float* rp1 = res + (size_t)(row0 + 8)*N + col;
                r00 = rp0[0]; r01 = rp0[1]; r10 = rp1[0]; r11 = rp1[1];
            }
            float2 o0, o1;
            o0.x = epi_apply(acc[mi][ni][0] + b0, r00, EPI);
            o0.y = epi_apply(acc[mi][ni][1] + b1, r01, EPI);
            o1.x = epi_apply(acc[mi][ni][2] + b0, r10, EPI);
            o1.y = epi_apply(acc[mi][ni][3] + b1, r11, EPI);
            *(float2*)cp0 = o0;
            *(float2*)cp1 = o1;
            if (WKT && col >= CC && col < 2*CC) {   // fused K transpose
                int kc = col - CC;
                Kt[(size_t)kc*TT + row0]           = o0.x;
                Kt[(size_t)(kc + 1)*TT + row0]     = o0.y;
                Kt[(size_t)kc*TT + row0 + 8]       = o1.x;
                Kt[(size_t)(kc + 1)*TT + row0 + 8] = o1.y;
            }
        }
    }
}

// ---------------- split-K reduce: out = sum4(part) + bias + res --------------
__global__ void reduce4(const float* __restrict__ part, const float* __restrict__ bias,
                        const float* __restrict__ res, float* __restrict__ out) {
    int idx = blockIdx.x*256 + threadIdx.x;     // 49152 float4s
    const int MN4 = TT*CC/4;
    const float4* p = (const float4*)part;
    float4 a = p[idx], b = p[idx + MN4], c = p[idx + 2*MN4], d = p[idx + 3*MN4];
    float4 bb = ((const float4*)bias)[idx & (CC/4 - 1)];
    float4 rr = ((const float4*)res)[idx];
    float4 o;
    o.x = a.x + b.x + c.x + d.x + bb.x + rr.x;
    o.y = a.y + b.y + c.y + d.y + bb.y + rr.y;
    o.z = a.z + b.z + c.z + d.z + bb.z + rr.z;
    o.w = a.w + b.w + c.w + d.w + bb.w + rr.w;
    ((float4*)out)[idx] = o;
}

// ---------------- gather attention v4: CTA per (4 i's, h) — K/V reuse x4 -----
// 128 threads. Pass1: thread-per-j, one K load feeds 4 query rows.
// Softmax: warp = row. Pass2: one V load feeds 4 rows.
__global__ void __launch_bounds__(128)
attn4(const float* __restrict__ qkv, const float* __restrict__ Kt,
      const int* __restrict__ bm,
      const float* __restrict__ EKt, const float* __restrict__ EV,
      const float* __restrict__ abe, float* __restrict__ y) {
    int ib = gridDim.x - 1 - blockIdx.x;  // heavy blocks first
    int i0 = ib * 4;
    int h = blockIdx.y;
    int tid = threadIdx.x;                // 128
    int lane = tid & 31, wid = tid >> 5;

    __shared__ float qe_s[4][DD*EE];      // [ii][d*16+e] = q[i0+ii][d]*EK[e][d]
    __shared__ float EV_s[EE*DD];         // [e][d]
    __shared__ float ab_s[EE];
    __shared__ float s_s[4][TT];          // scores -> probs (tail zeroed)
    __shared__ int   e_s[4][TT];
    __shared__ float psum[2][4][DD];
    __shared__ float resv[4];

    const float* EKh = EKt + h*DD*EE;     // EKt[h*1024 + d*16 + e]
    #pragma unroll
    for (int ii = 0; ii < 4; ii++) {
        const float* qrow = qkv + (size_t)(i0 + ii)*3*CC + h*DD;
        #pragma unroll
        for (int k = 0; k < 8; k++) {
            int idx = tid + k*128;
            qe_s[ii][idx] = __ldg(&qrow[idx >> 4]) * __ldg(&EKh[idx]);
        }
    }
    #pragma unroll
    for (int k = 0; k < 8; k++) {
        int idx = tid + k*128;
        EV_s[idx] = EV[(size_t)(idx >> 6)*CC + h*DD + (idx & 63)];
    }
    if (tid < EE) ab_s[tid] = abe[tid*HH + h];
    __syncthreads();

    const int jmax = i0 + 3;

    // ---- pass 1: thread-per-j; one Kt element serves 4 rows ----
    const float* KtH = Kt + (size_t)h*DD*TT;
    for (int j = tid; j <= jmax; j += 128) {
        int e0 = bm[(size_t)(i0+0)*TT + j];
        int e1 = bm[(size_t)(i0+1)*TT + j];
        int e2 = bm[(size_t)(i0+2)*TT + j];
        int e3 = bm[(size_t)(i0+3)*TT + j];
        const float* kp = KtH + j;
        float s0 = 0.f, s1 = 0.f, s2 = 0.f, s3 = 0.f;
        #pragma unroll 4
        for (int d = 0; d < DD; d++) {
            float kv = kp[(size_t)d*TT];
            s0 = fmaf(qe_s[0][d*EE + e0], kv, s0);
            s1 = fmaf(qe_s[1][d*EE + e1], kv, s1);
            s2 = fmaf(qe_s[2][d*EE + e2], kv, s2);
            s3 = fmaf(qe_s[3][d*EE + e3], kv, s3);
        }
        s_s[0][j] = s0 * 0.125f + ab_s[e0];  e_s[0][j] = e0;
        s_s[1][j] = s1 * 0.125f + ab_s[e1];  e_s[1][j] = e1;
        s_s[2][j] = s2 * 0.125f + ab_s[e2];  e_s[2][j] = e2;
        s_s[3][j] = s3 * 0.125f + ab_s[e3];  e_s[3][j] = e3;
    }
    __syncthreads();

    // ---- softmax: warp w owns row i0+w ----
    {
        int iw = i0 + wid;
        float lm = -1e30f;
        for (int j = lane; j <= iw; j += 32) lm = fmaxf(lm, s_s[wid][j]);
        #pragma unroll
        for (int o = 16; o > 0; o >>= 1) lm = fmaxf(lm, __shfl_xor_sync(0xffffffffu, lm, o));
        float ls = 0.f;
        for (int j = lane; j <= iw; j += 32) {
            float p = __expf(s_s[wid][j] - lm);
            s_s[wid][j] = p;
            ls += p;
        }
        #pragma unroll
        for (int o = 16; o > 0; o >>= 1) ls += __shfl_xor_sync(0xffffffffu, ls, o);
        if (lane == 0) resv[wid] = 1.0f / ls;
        // zero the ragged tail (i0+wid < j <= jmax) so pass2 runs unguarded
        for (int j = iw + 1 + lane; j <= jmax; j += 32) s_s[wid][j] = 0.f;
    }
    __syncthreads();

    // ---- pass 2: one V element serves 4 rows ----
    int d = tid & 63, half = tid >> 6;
    const float* qv = qkv + 2*CC + h*DD + d;
    const float* EVd = EV_s + d;
    float a0 = 0.f, a1 = 0.f, a2 = 0.f, a3 = 0.f;
    for (int j = half; j <= jmax; j += 2) {
        float v = qv[(size_t)j*3*CC];
        a0 = fmaf(s_s[0][j], v * EVd[e_s[0][j]*DD], a0);
        a1 = fmaf(s_s[1][j], v * EVd[e_s[1][j]*DD], a1);
        a2 = fmaf(s_s[2][j], v * EVd[e_s[2][j]*DD], a2);
        a3 = fmaf(s_s[3][j], v * EVd[e_s[3][j]*DD], a3);
    }
    psum[half][0][d] = a0;
    psum[half][1][d] = a1;
    psum[half][2][d] = a2;
    psum[half][3][d] = a3;
    __syncthreads();
    if (tid < DD) {
        #pragma unroll
        for (int ii = 0; ii < 4; ii++)
            y[(size_t)(i0 + ii)*CC + h*DD + tid] =
                (psum[0][ii][tid] + psum[1][ii][tid]) * resv[ii];
    }
}

// ---------------- host launch ------------------------------------------------
extern "C" void kernel_launch(void* const* d_in, const int* in_sizes, int n_in,
                              void* d_out, int out_size) {
    const float* x        = (const float*)d_in[0];
    const int*   bmx      = (const int*)  d_in[1];
    const float* ln1_w    = (const float*)d_in[2];
    const float* ln1_b    = (const float*)d_in[3];
    const float* w_attn_w = (const float*)d_in[4];
    const float* w_attn_b = (const float*)d_in[5];
    const float* w_proj_w = (const float*)d_in[6];
    const float* w_proj_b = (const float*)d_in[7];
    const float* abe      = (const float*)d_in[8];
    const float* edge_emb = (const float*)d_in[9];
    const float* wek      = (const float*)d_in[10];
    const float* bek      = (const float*)d_in[11];
    const float* wev      = (const float*)d_in[12];
    const float* bev      = (const float*)d_in[13];
    const float* ln2_w    = (const float*)d_in[14];
    const float* ln2_b    = (const float*)d_in[15];
    const float* c_fc_w   = (const float*)d_in[16];
    const float* c_fc_b   = (const float*)d_in[17];
    const float* c_proj_w = (const float*)d_in[18];
    const float* c_proj_b = (const float*)d_in[19];
    float* out = (float*)d_out;

    float *pH, *pQKV, *pEKt, *pEV, *pKt, *pY, *pX1, *pH2, *pFC, *pPart;
    cudaGetSymbolAddress((void**)&pH,    g_h);
    cudaGetSymbolAddress((void**)&pQKV,  g_qkv);
    cudaGetSymbolAddress((void**)&pEKt,  g_EKt);
    cudaGetSymbolAddress((void**)&pEV,   g_EV);
    cudaGetSymbolAddress((void**)&pKt,   g_Kt);
    cudaGetSymbolAddress((void**)&pY,    g_y);
    cudaGetSymbolAddress((void**)&pX1,   g_x1);
    cudaGetSymbolAddress((void**)&pH2,   g_h2);
    cudaGetSymbolAddress((void**)&pFC,   g_fc);
    cudaGetSymbolAddress((void**)&pPart, g_part);

    constexpr int SM64  = 3*(64  + 64)*36*4;  // 55296 B
    constexpr int SM128 = 3*(128 + 64)*36*4;  // 82944 B
    cudaFuncSetAttribute((const void*)gemm_pl<64,128,0,true >, cudaFuncAttributeMaxDynamicSharedMemorySize, SM64);
    cudaFuncSetAttribute((const void*)gemm_pl<128,256,2,false>, cudaFuncAttributeMaxDynamicSharedMemorySize, SM128);
    cudaFuncSetAttribute((const void*)gemm_pl<64,128,3,false>, cudaFuncAttributeMaxDynamicSharedMemorySize, SM64);

    // 1. edge tables
    edge_pre<<<EE, CC>>>(edge_emb, wek, bek, wev, bev, pEKt, pEV);
    // 2. LN1
    ln_kernel<<<TT, 256>>>(x, ln1_w, ln1_b, pH);
    // 3. QKV = LN1 @ w_attn^T + b (384 x 1536 x 512), fused K-transpose
    gemm_pl<64,128,0,true><<<dim3(3*CC/64, TT/64), 128, SM64>>>(
        pH, w_attn_w, w_attn_b, nullptr, pQKV, pKt, TT, 3*CC, CC, CC);
    // 4. gather attention (4 query rows per CTA — K/V traffic / 4)
    attn4<<<dim3(TT/4, HH), 128>>>(pQKV, pKt, bmx, pEKt, pEV, abe, pY);
    // 5. x1 = x + y @ w_proj^T + b (split-K=4: 192 blocks)
    gemm_pl<64,128,3,false><<<dim3(CC/64, TT/64, 4), 128, SM64>>>(
        pY, w_proj_w, nullptr, nullptr, pPart, nullptr, TT, CC, CC, CC/4);
    reduce4<<<TT*CC/1024, 256>>>(pPart, w_proj_b, x, pX1);
    // 6. LN2
    ln_kernel<<<TT, 256>>>(pX1, ln2_w, ln2_b, pH2);
    // 7. fc = gelu(h2 @ c_fc^T + b) — BM=128: 96 CTAs, one wave
    gemm_pl<128,256,2,false><<<dim3(4*CC/64, TT/128), 256, SM128>>>(
        pH2, c_fc_w, c_fc_b, nullptr, pFC, nullptr, TT, 4*CC, CC, CC);
    // 8. out = x1 + fc @ c_proj^T + b (split-K=4: 192 blocks, K=512 each)
    gemm_pl<64,128,3,false><<<dim3(CC/64, TT/64, 4), 128, SM64>>>(
        pFC, c_proj_w, nullptr, nullptr, pPart, nullptr, TT, CC, 4*CC, CC);
    reduce4<<<TT*CC/1024, 256>>>(pPart, c_proj_b, pX1, out);
}